// round 14
// baseline (speedup 1.0000x reference)
#include <cuda_runtime.h>
#include <cuda_bf16.h>
#include <math.h>
#include <stdint.h>

#define BB 64
#define NNODES 128
#define HH 32
#define HEc 64
#define OEc 32
#define NT (BB*NNODES)
#define ALPHA 0.1f
#define BNEPS 1e-5f

static const double NE_D = 1048576.0;  // B*N*N edges
static const double NT_D = 8192.0;     // B*N nodes

// ----------------- device scratch (no allocs allowed) -----------------
__device__ __align__(16) float g_x[NT*HH];
__device__ __align__(16) float g_Q1[NT*HEc];
__device__ __align__(16) float g_P2[NT*HEc];
__device__ __align__(16) float g_Sagg[NT*OEc];
__device__ __align__(16) float g_h1[NT*HH];
__device__ __align__(16) float g_h2[NT*HH];
__device__ __align__(16) float2 g_de[BB*NNODES*NNODES];  // 8MB (dist,int)
__device__ double g_su[HEc],  g_ssu[HEc];
__device__ double g_sv[OEc],  g_ssv[OEc];
__device__ double g_sh0[HH],  g_ssh0[HH];
__device__ double g_sh1[HH],  g_ssh1[HH];

__device__ __forceinline__ float lrelu(float z){ return fmaxf(z, ALPHA*z); }

// ---------------- warp-MMA helpers (base ISA: sm_80+) -------------------
__device__ __forceinline__ uint32_t s2u(const void* p){
    return (uint32_t)__cvta_generic_to_shared(p);
}
__device__ __forceinline__ void ldmx4(uint32_t* r, uint32_t a){
    asm volatile("ldmatrix.sync.aligned.m8n8.x4.shared.b16 {%0,%1,%2,%3}, [%4];"
        : "=r"(r[0]),"=r"(r[1]),"=r"(r[2]),"=r"(r[3]) : "r"(a));
}
__device__ __forceinline__ void ldmx2(uint32_t* r, uint32_t a){
    asm volatile("ldmatrix.sync.aligned.m8n8.x2.shared.b16 {%0,%1}, [%2];"
        : "=r"(r[0]),"=r"(r[1]) : "r"(a));
}
__device__ __forceinline__ void mma16816(float* c, const uint32_t* a, const uint32_t* b){
    asm volatile("mma.sync.aligned.m16n8k16.row.col.f32.bf16.bf16.f32 "
        "{%0,%1,%2,%3}, {%4,%5,%6,%7}, {%8,%9}, {%0,%1,%2,%3};"
        : "+f"(c[0]),"+f"(c[1]),"+f"(c[2]),"+f"(c[3])
        : "r"(a[0]),"r"(a[1]),"r"(a[2]),"r"(a[3]), "r"(b[0]),"r"(b[1]));
}

// ----------------------------------------------------------------------
__global__ void k_pad(const float* __restrict__ xin){
    int i = blockIdx.x*256 + threadIdx.x;
    if (blockIdx.x == 0){
        int t = threadIdx.x;
        if (t < 64){ g_su[t]=0.0; g_ssu[t]=0.0; }
        if (t < 32){ g_sv[t]=0.0; g_ssv[t]=0.0;
                     g_sh0[t]=0.0; g_ssh0[t]=0.0;
                     g_sh1[t]=0.0; g_ssh1[t]=0.0; }
    }
    if (i < NT*HH){
        int node = i >> 5, k = i & 31;
        g_x[i] = (k < 3) ? xin[node*3 + k] : 0.0f;
    }
}

// Q1 = x@Wah[0:32] + bah ; P2 = x@Wah[32:64]   (standalone: step 0 only)
__global__ void __launch_bounds__(256) k_pre(const float* __restrict__ Wah_i,
                                             const float* __restrict__ bah_i){
    __shared__ float xs[64*33];
    __shared__ float W1s[32*64];
    __shared__ float W2s[32*64];
    __shared__ float bs[64];
    int t = threadIdx.x;
    int n0 = blockIdx.x*64;
    for (int idx=t; idx<64*32; idx+=256){
        int n = idx>>5, k = idx&31;
        xs[n*33+k] = g_x[(n0+n)*32 + k];
    }
    for (int idx=t; idx<32*64; idx+=256){
        int k = idx>>6, c = idx&63;
        W1s[idx] = Wah_i[k*64 + c];
        W2s[idx] = Wah_i[(32+k)*64 + c];
    }
    if (t < 64) bs[t] = bah_i[t];
    __syncthreads();
    int c = t & 63, ng = t >> 6;
    for (int n=ng; n<64; n+=4){
        float q = bs[c], p = 0.0f;
        #pragma unroll
        for (int k=0;k<32;k++){
            float xv = xs[n*33+k];
            q = fmaf(xv, W1s[k*64+c], q);
            p = fmaf(xv, W2s[k*64+c], p);
        }
        g_Q1[(n0+n)*64 + c] = q;
        g_P2[(n0+n)*64 + c] = p;
    }
}

// ---------------- edge pass 1: stats of u + de producer ----------------
__global__ void __launch_bounds__(256) k_edge_stats(const float* __restrict__ Wah_i){
    extern __shared__ float sm[];
    float*  xr  = sm;                       // 4224
    float2* de  = (float2*)(xr + 4224);     // 2048 float2
    float*  red = (float*)(de + 2048);      // 256

    int t  = threadIdx.x;
    int b  = blockIdx.y;
    int a0 = blockIdx.x*16;

    // zero g_sh1 accumulators for this step (consumed by previous node2)
    if (blockIdx.x == 0 && blockIdx.y == 0 && t < 32){
        g_sh1[t]=0.0; g_ssh1[t]=0.0;
    }

    for (int idx=t; idx<4096; idx+=256){
        int r = idx>>5, kk = idx&31;
        xr[r*33+kk] = g_x[b*4096 + idx];
    }
    __syncthreads();

    #pragma unroll
    for (int j=0;j<8;j++){
        int e  = t + 256*j;
        int as = e >> 7, p = e & 127;
        const float* xra = xr + (a0+as)*33;
        const float* xrp = xr + p*33;
        float s = 0.0f;
        #pragma unroll
        for (int kk=0;kk<31;kk++){
            float df = xrp[kk] - xra[kk] + 1e-12f;
            s = fmaf(df, df, s);
        }
        float2 v = make_float2(sqrtf(s), 1.0f - (xrp[31]-xra[31]));
        de[e] = v;
        g_de[(size_t)(b*128 + a0 + as)*128 + p] = v;
    }
    __syncthreads();

    int k = t & 63, g = t >> 6;
    const float* P2b = g_P2 + (size_t)b*8192;
    float wdk = __ldg(Wah_i + 64*64 + k);
    float wik = __ldg(Wah_i + 65*64 + k);
    float q[16];
    #pragma unroll
    for (int as=0; as<16; as++) q[as] = __ldg(&g_Q1[(size_t)(b*128+a0+as)*64 + k]);

    float su = 0.0f, ssu = 0.0f;
    float pvn = __ldg(&P2b[g*64 + k]);
    #pragma unroll 2
    for (int m=0; m<32; m++){
        float pv = pvn;
        if (m < 31) pvn = __ldg(&P2b[(g + 4*(m+1))*64 + k]);
        int p = g + 4*m;
        #pragma unroll
        for (int as=0; as<16; as++){
            float2 e2 = de[as*128+p];
            float z = fmaf(e2.x, wdk, q[as] + pv);
            z = fmaf(e2.y, wik, z);
            float u = fmaxf(z, ALPHA*z);
            su += u; ssu = fmaf(u,u,ssu);
        }
    }
    red[g*64+k] = su;
    __syncthreads();
    if (g == 0)
        atomicAdd(&g_su[k], (double)(red[k]+red[64+k]+red[128+k]+red[192+k]));
    __syncthreads();
    red[g*64+k] = ssu;
    __syncthreads();
    if (g == 0)
        atomicAdd(&g_ssu[k], (double)(red[k]+red[64+k]+red[128+k]+red[192+k]));
}

// ---------------- edge pass 2: HMMA main (slim smem, de from gmem) -----
// byte offsets from 1024-aligned base
#define OFF_UHI   0        // 18432 (rows 144B)
#define OFF_ULO   18432    // 18432
#define OFF_WTHI  36864    // 4608 (32 rows x 144B)
#define OFF_WTLO  41472    // 4608
#define OFF_RED   46080    // 4096 (2 buffers x (256 sum + 256 sq))
#define OFF_BAF   50176    // 128
#define OFF_S1    50304    // 256
#define OFF_T1    50560    // 256
#define SMEM_MAIN_BYTES (1024 + 50816)
#define ROWB 144

__global__ void __launch_bounds__(256, 2) k_edge_main(
        const float* __restrict__ Wah_i,
        const float* __restrict__ Wa_i,  const float* __restrict__ ba_i,
        const float* __restrict__ geh_i, const float* __restrict__ beh_i){
    extern __shared__ char smraw[];
    char* A0 = (char*)(((uintptr_t)smraw + 1023) & ~(uintptr_t)1023);

    char*   uhi  = A0 + OFF_UHI;
    char*   ulo  = A0 + OFF_ULO;
    char*   wthi = A0 + OFF_WTHI;
    char*   wtlo = A0 + OFF_WTLO;
    float*  redb = (float*)(A0 + OFF_RED); // [2][512]
    float*  bafs = (float*)(A0 + OFF_BAF);
    float*  s1   = (float*)(A0 + OFF_S1);
    float*  t1   = (float*)(A0 + OFF_T1);

    int t    = threadIdx.x;
    int w    = t >> 5, lane = t & 31;
    int b    = blockIdx.y;
    int a0   = blockIdx.x*32;

    // --- prologue: BN1 scale/shift ---
    if (t < 64){
        double m = g_su[t]/NE_D;
        double v = g_ssu[t]/NE_D - m*m;
        float s = geh_i[t] * rsqrtf((float)v + BNEPS);
        s1[t] = s; t1[t] = beh_i[t] - (float)m*s;
    }
    __syncthreads();

    // --- W split + bias fold ---
    for (int idx=t; idx<2048; idx+=256){
        int c = idx>>6, k = idx&63;
        float wv = s1[k]*Wa_i[k*32+c];
        __nv_bfloat16 hi = __float2bfloat16(wv);
        *(__nv_bfloat16*)(wthi + c*ROWB + k*2) = hi;
        *(__nv_bfloat16*)(wtlo + c*ROWB + k*2) =
            __float2bfloat16(wv - __bfloat162float(hi));
    }
    if (t < 32){
        float acc = ba_i[t];
        #pragma unroll
        for (int k=0;k<64;k++) acc = fmaf(t1[k], Wa_i[k*32+t], acc);
        bafs[t] = acc;
    }
    __syncthreads();

    // --- persistent B fragments (W^T hi+lo), per warp ---
    uint32_t bh[4][4][2], bl[4][4][2];
    {
        int li = lane & 15;
        uint32_t rsel = (uint32_t)((li & 7)*ROWB);
        uint32_t ksel = (uint32_t)((li >> 3)*16);
        #pragma unroll
        for (int kt=0; kt<4; kt++){
            #pragma unroll
            for (int nt=0; nt<4; nt++){
                uint32_t off = (uint32_t)(nt*8*ROWB) + rsel + (uint32_t)(kt*32) + ksel;
                ldmx2(bh[kt][nt], s2u(wthi) + off);
                ldmx2(bl[kt][nt], s2u(wtlo) + off);
            }
        }
    }
    int tc = lane & 3;
    float bias0[4], bias1[4];
    #pragma unroll
    for (int nt=0; nt<4; nt++){
        bias0[nt] = bafs[8*nt + 2*tc];
        bias1[nt] = bafs[8*nt + 2*tc + 1];
    }

    // phase-A per-thread constants
    int kp = lane;                         // k-pair 0..31
    float wd0 = __ldg(Wah_i + 64*64 + 2*kp), wd1 = __ldg(Wah_i + 64*64 + 2*kp + 1);
    float wi0 = __ldg(Wah_i + 65*64 + 2*kp), wi1 = __ldg(Wah_i + 65*64 + 2*kp + 1);
    const float2* P2b = (const float2*)(g_P2 + (size_t)b*8192);
    const float2* Q1b = (const float2*)(g_Q1 + (size_t)(b*128 + a0)*64);
    const float2* deB = g_de + (size_t)(b*128 + a0)*128;

    uint32_t aoff = (uint32_t)((w*16 + (lane & 15))*ROWB) + ((lane & 16) ? 16u : 0u);
    uint32_t uhiB = s2u(uhi), uloB = s2u(ulo);

    float vtot = 0.0f, ssvtot = 0.0f;      // t<32 only

    for (int as=0; as<32; as++){
        // ---- phase A: u -> bf16 hi/lo tiles ----
        {
            float2 q = __ldg(&Q1b[as*32 + kp]);
            #pragma unroll
            for (int j=0;j<16;j++){
                int p = w + 8*j;
                float2 pv = __ldg(&P2b[p*32 + kp]);
                float2 dd = __ldg(&deB[(size_t)as*128 + p]);
                float z0 = fmaf(dd.x, wd0, q.x + pv.x); z0 = fmaf(dd.y, wi0, z0);
                float z1 = fmaf(dd.x, wd1, q.y + pv.y); z1 = fmaf(dd.y, wi1, z1);
                float u0 = fmaxf(z0, ALPHA*z0);
                float u1 = fmaxf(z1, ALPHA*z1);
                __nv_bfloat162 h2 = __floats2bfloat162_rn(u0, u1);
                float2 hf = __bfloat1622float2(h2);
                __nv_bfloat162 l2 = __floats2bfloat162_rn(u0 - hf.x, u1 - hf.y);
                *(__nv_bfloat162*)(uhi + p*ROWB + kp*4) = h2;
                *(__nv_bfloat162*)(ulo + p*ROWB + kp*4) = l2;
            }
        }
        // ---- drain previous iteration's reduction (overlaps phase A) ----
        if (as > 0 && t < 32){
            const float* rb0 = redb + ((as-1)&1)*512;
            float S = 0.0f, SS = 0.0f;
            #pragma unroll
            for (int j=0;j<8;j++){ S += rb0[j*32 + t]; SS += rb0[256 + j*32 + t]; }
            g_Sagg[(size_t)(b*128 + a0 + as - 1)*32 + t] = S;
            vtot += S; ssvtot += SS;
        }
        __syncthreads();   // u tiles ready; red[(as-1)&1] drained

        // ---- phase B: 3-pass bf16 HMMA, accumulate fp32 ----
        float C[4][4];
        #pragma unroll
        for (int nt=0;nt<4;nt++){
            C[nt][0]=0.f; C[nt][1]=0.f; C[nt][2]=0.f; C[nt][3]=0.f;
        }
        #pragma unroll
        for (int kt=0; kt<4; kt++){
            uint32_t ah[4], al[4];
            ldmx4(ah, uhiB + aoff + kt*32);
            ldmx4(al, uloB + aoff + kt*32);
            #pragma unroll
            for (int nt=0; nt<4; nt++){
                mma16816(C[nt], ah, bh[kt][nt]);
                mma16816(C[nt], ah, bl[kt][nt]);
                mma16816(C[nt], al, bh[kt][nt]);
            }
        }

        // ---- epilogue: bias + lrelu, row-sum + sq-sum per channel ----
        float* rb = redb + (as&1)*512;
        #pragma unroll
        for (int nt=0; nt<4; nt++){
            float y00 = C[nt][0] + bias0[nt];
            float y01 = C[nt][1] + bias1[nt];
            float y10 = C[nt][2] + bias0[nt];
            float y11 = C[nt][3] + bias1[nt];
            float v00 = fmaxf(y00, ALPHA*y00);
            float v01 = fmaxf(y01, ALPHA*y01);
            float v10 = fmaxf(y10, ALPHA*y10);
            float v11 = fmaxf(y11, ALPHA*y11);
            float cs0 = v00 + v10, cs1 = v01 + v11;
            float sq0 = fmaf(v00,v00, v10*v10);
            float sq1 = fmaf(v01,v01, v11*v11);
            #pragma unroll
            for (int off=4; off<32; off<<=1){
                cs0 += __shfl_xor_sync(0xFFFFFFFFu, cs0, off);
                cs1 += __shfl_xor_sync(0xFFFFFFFFu, cs1, off);
                sq0 += __shfl_xor_sync(0xFFFFFFFFu, sq0, off);
                sq1 += __shfl_xor_sync(0xFFFFFFFFu, sq1, off);
            }
            if (lane < 4){
                rb[w*32 + 8*nt + 2*tc]       = cs0;
                rb[w*32 + 8*nt + 2*tc + 1]   = cs1;
                rb[256 + w*32 + 8*nt + 2*tc]     = sq0;
                rb[256 + w*32 + 8*nt + 2*tc + 1] = sq1;
            }
        }
        __syncthreads();   // red[as&1] complete; u tiles consumed
    }

    // final drain (as=31)
    if (t < 32){
        const float* rb0 = redb + (31&1)*512;
        float S = 0.0f, SS = 0.0f;
        #pragma unroll
        for (int j=0;j<8;j++){ S += rb0[j*32 + t]; SS += rb0[256 + j*32 + t]; }
        g_Sagg[(size_t)(b*128 + a0 + 31)*32 + t] = S;
        vtot += S; ssvtot += SS;
        atomicAdd(&g_sv[t],  (double)vtot);
        atomicAdd(&g_ssv[t], (double)ssvtot);
    }
}

// ---------------- node layer 0 (staged, coalesced) ---------------------
__global__ void __launch_bounds__(128) k_node0(const float* __restrict__ Wn0_i,
                                               const float* __restrict__ bn0_i,
                                               const float* __restrict__ ge_i,
                                               const float* __restrict__ be_i){
    __shared__ float W[2048];
    __shared__ float sA[4096];
    __shared__ float sX[4096];
    __shared__ float s2[32], t2[32], bsh[32], ssum[32], sssum[32];
    int t = threadIdx.x;
    int row0 = blockIdx.x*128;
    if (t < 32){
        double m = g_sv[t]/NE_D;
        double v = g_ssv[t]/NE_D - m*m;
        float s = ge_i[t] * rsqrtf((float)v + BNEPS);
        s2[t] = s; t2[t] = be_i[t] - (float)m*s;
        bsh[t] = bn0_i[t]; ssum[t] = 0.0f; sssum[t] = 0.0f;
    }
    // zero g_su/g_ssu for next step's stats (main already consumed them)
    if (blockIdx.x == 0 && t >= 32 && t < 96){
        g_su[t-32] = 0.0; g_ssu[t-32] = 0.0;
    }
    for (int idx=t; idx<512; idx+=128)
        ((float4*)W)[idx] = ((const float4*)Wn0_i)[idx];
    for (int idx=t; idx<1024; idx+=128){
        ((float4*)sA)[idx] = ((const float4*)(g_Sagg + (size_t)row0*32))[idx];
        ((float4*)sX)[idx] = ((const float4*)(g_x    + (size_t)row0*32))[idx];
    }
    __syncthreads();

    float in[64];
    #pragma unroll
    for (int cc=0;cc<32;cc++){
        in[cc]    = fmaf(s2[cc], sA[t*32+cc], 128.0f*t2[cc]);
        in[32+cc] = sX[t*32+cc];
    }
    float z[32];
    #pragma unroll
    for (int cc=0;cc<32;cc++) z[cc] = bsh[cc];
    const float4* W4 = (const float4*)W;
    #pragma unroll
    for (int kk=0;kk<64;kk++){
        float xv = in[kk];
        #pragma unroll
        for (int j=0;j<8;j++){
            float4 wv = W4[kk*8+j];
            z[4*j+0] = fmaf(xv, wv.x, z[4*j+0]);
            z[4*j+1] = fmaf(xv, wv.y, z[4*j+1]);
            z[4*j+2] = fmaf(xv, wv.z, z[4*j+2]);
            z[4*j+3] = fmaf(xv, wv.w, z[4*j+3]);
        }
    }
    int lane = t & 31;
    #pragma unroll
    for (int cc=0;cc<32;cc++){
        float h = lrelu(z[cc]);
        sA[t*32+cc] = h;
        float v1 = h, v2 = h*h;
        #pragma unroll
        for (int off=16; off>0; off>>=1){
            v1 += __shfl_xor_sync(0xFFFFFFFFu, v1, off);
            v2 += __shfl_xor_sync(0xFFFFFFFFu, v2, off);
        }
        if (lane == 0){ atomicAdd(&ssum[cc], v1); atomicAdd(&sssum[cc], v2); }
    }
    __syncthreads();
    for (int idx=t; idx<1024; idx+=128)
        ((float4*)(g_h1 + (size_t)row0*32))[idx] = ((float4*)sA)[idx];
    if (t < 32){
        atomicAdd(&g_sh0[t], (double)ssum[t]);
        atomicAdd(&g_ssh0[t], (double)sssum[t]);
    }
}

// ---------------- node layer 1 -----------------------------------------
__global__ void __launch_bounds__(128) k_node1(const float* __restrict__ Wn_i,
                                               const float* __restrict__ bnn_i,
                                               const float* __restrict__ gn0,
                                               const float* __restrict__ bn0v){
    __shared__ float W[1024];
    __shared__ float sH[4096];
    __shared__ float s0[32], t0[32], bsh[32], ssum[32], sssum[32];
    int t = threadIdx.x;
    int row0 = blockIdx.x*128;
    if (t < 32){
        double m = g_sh0[t]/NT_D;
        double v = g_ssh0[t]/NT_D - m*m;
        float s = gn0[t] * rsqrtf((float)v + BNEPS);
        s0[t] = s; t0[t] = bn0v[t] - (float)m*s;
        bsh[t] = bnn_i[t]; ssum[t] = 0.0f; sssum[t] = 0.0f;
    }
    // zero g_sv/g_ssv for next step's main (node0 already consumed them)
    if (blockIdx.x == 0 && t >= 32 && t < 64){
        g_sv[t-32] = 0.0; g_ssv[t-32] = 0.0;
    }
    for (int idx=t; idx<256; idx+=128)
        ((float4*)W)[idx] = ((const float4*)Wn_i)[idx];
    for (int idx=t; idx<1024; idx+=128)
        ((float4*)sH)[idx] = ((const float4*)(g_h1 + (size_t)row0*32))[idx];
    __syncthreads();

    float hn[32];
    #pragma unroll
    for (int kk=0;kk<32;kk++) hn[kk] = fmaf(s0[kk], sH[t*32+kk], t0[kk]);
    float z[32];
    #pragma unroll
    for (int cc=0;cc<32;cc++) z[cc] = bsh[cc];
    const float4* W4 = (const float4*)W;
    #pragma unroll
    for (int kk=0;kk<32;kk++){
        float xv = hn[kk];
        #pragma unroll
        for (int j=0;j<8;j++){
            float4 wv = W4[kk*8+j];
            z[4*j+0] = fmaf(xv, wv.x, z[4*j+0]);
            z[4*j+1] = fmaf(xv, wv.y, z[4*j+1]);
            z[4*j+2] = fmaf(xv, wv.z, z[4*j+2]);
            z[4*j+3] = fmaf(xv, wv.w, z[4*j+3]);
        }
    }
    int lane = t & 31;
    #pragma unroll
    for (int cc=0;cc<32;cc++){
        float h = lrelu(z[cc]);
        sH[t*32+cc] = h;
        float v1 = h, v2 = h*h;
        #pragma unroll
        for (int off=16; off>0; off>>=1){
            v1 += __shfl_xor_sync(0xFFFFFFFFu, v1, off);
            v2 += __shfl_xor_sync(0xFFFFFFFFu, v2, off);
        }
        if (lane == 0){ atomicAdd(&ssum[cc], v1); atomicAdd(&sssum[cc], v2); }
    }
    __syncthreads();
    for (int idx=t; idx<1024; idx+=128)
        ((float4*)(g_h2 + (size_t)row0*32))[idx] = ((float4*)sH)[idx];
    if (t < 32){
        atomicAdd(&g_sh1[t], (double)ssum[t]);
        atomicAdd(&g_ssh1[t], (double)sssum[t]);
    }
}

// ---------------- node final: update linear + tanh (+fused pre) --------
__global__ void __launch_bounds__(128) k_node2(const float* __restrict__ Wu_i,
                                               const float* __restrict__ bu_i,
                                               const float* __restrict__ gn1,
                                               const float* __restrict__ bn1v,
                                               float* __restrict__ out,
                                               int is_last,
                                               const float* __restrict__ Wah_n,
                                               const float* __restrict__ bah_n){
    __shared__ float W[1024];
    __shared__ float sH[4096];
    __shared__ float W1s[2048];
    __shared__ float W2s[2048];
    __shared__ float bs[64];
    __shared__ float s0[32], t0[32], bsh[32];
    int t = threadIdx.x;
    int row0 = blockIdx.x*128;
    if (t < 32){
        double m = g_sh1[t]/NT_D;
        double v = g_ssh1[t]/NT_D - m*m;
        float s = gn1[t] * rsqrtf((float)v + BNEPS);
        s0[t] = s; t0[t] = bn1v[t] - (float)m*s;
        bsh[t] = bu_i[t];
    }
    // zero g_sh0/g_ssh0 for next step's node0 (node1 already consumed them)
    if (blockIdx.x == 0 && t >= 32 && t < 64){
        g_sh0[t-32] = 0.0; g_ssh0[t-32] = 0.0;
    }
    for (int idx=t; idx<256; idx+=128)
        ((float4*)W)[idx] = ((const float4*)Wu_i)[idx];
    for (int idx=t; idx<1024; idx+=128)
        ((float4*)sH)[idx] = ((const float4*)(g_h2 + (size_t)row0*32))[idx];
    if (!is_last){
        for (int idx=t; idx<2048; idx+=128){
            int k = idx>>6, c = idx&63;
            W1s[idx] = Wah_n[k*64 + c];
            W2s[idx] = Wah_n[(32+k)*64 + c];
        }
        if (t < 64) bs[t] = bah_n[t];
    }
    __syncthreads();

    float hn[32];
    #pragma unroll
    for (int kk=0;kk<32;kk++) hn[kk] = fmaf(s0[kk], sH[t*32+kk], t0[kk]);
    float z[32];
    #pragma unroll
    for (int cc=0;cc<32;cc++) z[cc] = bsh[cc];
    const float4* W4 = (const float4*)W;
    #pragma unroll
    for (int kk=0;kk<32;kk++){
        float xv = hn[kk];
        #pragma unroll
        for (int j=0;j<8;j++){
            float4 wv = W4[kk*8+j];
            z[4*j+0] = fmaf(xv, wv.x, z[4*j+0]);
            z[4*j+1] = fmaf(xv, wv.y, z[4*j+1]);
            z[4*j+2] = fmaf(xv, wv.z, z[4*j+2]);
            z[4*j+3] = fmaf(xv, wv.w, z[4*j+3]);
        }
    }
    __syncthreads();
    #pragma unroll
    for (int cc=0;cc<32;cc++) sH[t*32+cc] = tanhf(z[cc]);
    __syncthreads();
    for (int idx=t; idx<1024; idx+=128){
        float4 o4 = ((float4*)sH)[idx];
        ((float4*)(g_x + (size_t)row0*32))[idx] = o4;
        if (is_last) ((float4*)(out + (size_t)row0*32))[idx] = o4;
    }

    // ---- fused pre for next step: Q1/P2 of this block's 128 rows ----
    if (!is_last){
        int c = t & 63, ng = t >> 6;       // 2 groups of 64 channels
        for (int n=ng; n<128; n+=2){
            const float* xrow = sH + n*32;
            float q = bs[c], p = 0.0f;
            #pragma unroll
            for (int k=0;k<32;k++){
                float xv = xrow[k];
                q = fmaf(xv, W1s[k*64+c], q);
                p = fmaf(xv, W2s[k*64+c], p);
            }
            g_Q1[(size_t)(row0+n)*64 + c] = q;
            g_P2[(size_t)(row0+n)*64 + c] = p;
        }
    }
}

// ----------------------------------------------------------------------
extern "C" void kernel_launch(void* const* d_in, const int* in_sizes, int n_in,
                              void* d_out, int out_size){
    const float* x    = (const float*)d_in[0];
    const float* Wah  = (const float*)d_in[1];
    const float* bah  = (const float*)d_in[2];
    const float* Wa   = (const float*)d_in[3];
    const float* ba   = (const float*)d_in[4];
    const float* geh  = (const float*)d_in[5];
    const float* beh  = (const float*)d_in[6];
    const float* ge   = (const float*)d_in[7];
    const float* be   = (const float*)d_in[8];
    const float* Wn0  = (const float*)d_in[9];
    const float* bn0  = (const float*)d_in[10];
    const float* Wn   = (const float*)d_in[11];
    const float* bnn  = (const float*)d_in[12];
    const float* gn   = (const float*)d_in[13];
    const float* bnv  = (const float*)d_in[14];
    const float* Wu   = (const float*)d_in[15];
    const float* bu   = (const float*)d_in[16];
    float* out = (float*)d_out;

    const size_t SMEM_STATS = (4224 + 4096 + 256)*sizeof(float);   // 34304
    cudaFuncSetAttribute(k_edge_stats, cudaFuncAttributeMaxDynamicSharedMemorySize, (int)SMEM_STATS);
    cudaFuncSetAttribute(k_edge_main,  cudaFuncAttributeMaxDynamicSharedMemorySize, SMEM_MAIN_BYTES);

    k_pad<<<NT*HH/256, 256>>>(x);
    k_pre<<<128,256>>>(Wah, bah);

    for (int i=0; i<4; i++){
        int inx = (i < 3) ? (i+1) : 0;     // next-step weight index (unused if last)
        k_edge_stats<<<dim3(8,64),256,SMEM_STATS>>>(Wah + i*66*64);
        k_edge_main<<<dim3(4,64),256,SMEM_MAIN_BYTES>>>(Wah + i*66*64,
                                                        Wa + i*64*32, ba + i*32,
                                                        geh + i*64, beh + i*64);
        k_node0<<<64,128>>>(Wn0 + i*64*32, bn0 + i*32, ge + i*32, be + i*32);
        k_node1<<<64,128>>>(Wn + i*32*32, bnn + i*32, gn + (i*2+0)*32, bnv + (i*2+0)*32);
        k_node2<<<64,128>>>(Wu + i*32*32, bu + i*32, gn + (i*2+1)*32, bnv + (i*2+1)*32,
                            out, (i==3) ? 1 : 0,
                            Wah + inx*66*64, bah + inx*64);
    }
}

// round 15
// speedup vs baseline: 1.0445x; 1.0445x over previous
#include <cuda_runtime.h>
#include <cuda_bf16.h>
#include <math.h>
#include <stdint.h>

#define BB 64
#define NNODES 128
#define HH 32
#define HEc 64
#define OEc 32
#define NT (BB*NNODES)
#define ALPHA 0.1f
#define BNEPS 1e-5f

static const double NE_D = 1048576.0;  // B*N*N edges
static const double NT_D = 8192.0;     // B*N nodes

// ----------------- device scratch (no allocs allowed) -----------------
__device__ __align__(16) float g_x[NT*HH];
__device__ __align__(16) float g_Q1[NT*HEc];
__device__ __align__(16) float g_P2[NT*HEc];
__device__ __align__(16) float g_Sagg[NT*OEc];
__device__ __align__(16) float g_h1[NT*HH];
__device__ __align__(16) float g_h2[NT*HH];
__device__ double g_su[HEc],  g_ssu[HEc];
__device__ double g_sv[OEc],  g_ssv[OEc];
__device__ double g_sh0[HH],  g_ssh0[HH];
__device__ double g_sh1[HH],  g_ssh1[HH];

__device__ __forceinline__ float lrelu(float z){ return fmaxf(z, ALPHA*z); }

// ---------------- warp-MMA helpers (base ISA: sm_80+) -------------------
__device__ __forceinline__ uint32_t s2u(const void* p){
    return (uint32_t)__cvta_generic_to_shared(p);
}
__device__ __forceinline__ void ldmx4(uint32_t* r, uint32_t a){
    asm volatile("ldmatrix.sync.aligned.m8n8.x4.shared.b16 {%0,%1,%2,%3}, [%4];"
        : "=r"(r[0]),"=r"(r[1]),"=r"(r[2]),"=r"(r[3]) : "r"(a));
}
__device__ __forceinline__ void ldmx2(uint32_t* r, uint32_t a){
    asm volatile("ldmatrix.sync.aligned.m8n8.x2.shared.b16 {%0,%1}, [%2];"
        : "=r"(r[0]),"=r"(r[1]) : "r"(a));
}
__device__ __forceinline__ void mma16816(float* c, const uint32_t* a, const uint32_t* b){
    asm volatile("mma.sync.aligned.m16n8k16.row.col.f32.bf16.bf16.f32 "
        "{%0,%1,%2,%3}, {%4,%5,%6,%7}, {%8,%9}, {%0,%1,%2,%3};"
        : "+f"(c[0]),"+f"(c[1]),"+f"(c[2]),"+f"(c[3])
        : "r"(a[0]),"r"(a[1]),"r"(a[2]),"r"(a[3]), "r"(b[0]),"r"(b[1]));
}

// ----------------------------------------------------------------------
__global__ void k_pad(const float* __restrict__ xin){
    int i = blockIdx.x*256 + threadIdx.x;
    if (blockIdx.x == 0){
        int t = threadIdx.x;
        if (t < 64){ g_su[t]=0.0; g_ssu[t]=0.0; }
        if (t < 32){ g_sv[t]=0.0; g_ssv[t]=0.0;
                     g_sh0[t]=0.0; g_ssh0[t]=0.0;
                     g_sh1[t]=0.0; g_ssh1[t]=0.0; }
    }
    if (i < NT*HH){
        int node = i >> 5, k = i & 31;
        g_x[i] = (k < 3) ? xin[node*3 + k] : 0.0f;
    }
}

// Q1 = x@Wah[0:32] + bah ; P2 = x@Wah[32:64]   (standalone: step 0 only)
__global__ void __launch_bounds__(256) k_pre(const float* __restrict__ Wah_i,
                                             const float* __restrict__ bah_i){
    __shared__ float xs[64*33];
    __shared__ float W1s[32*64];
    __shared__ float W2s[32*64];
    __shared__ float bs[64];
    int t = threadIdx.x;
    int n0 = blockIdx.x*64;
    for (int idx=t; idx<64*32; idx+=256){
        int n = idx>>5, k = idx&31;
        xs[n*33+k] = g_x[(n0+n)*32 + k];
    }
    for (int idx=t; idx<32*64; idx+=256){
        int k = idx>>6, c = idx&63;
        W1s[idx] = Wah_i[k*64 + c];
        W2s[idx] = Wah_i[(32+k)*64 + c];
    }
    if (t < 64) bs[t] = bah_i[t];
    __syncthreads();
    int c = t & 63, ng = t >> 6;
    for (int n=ng; n<64; n+=4){
        float q = bs[c], p = 0.0f;
        #pragma unroll
        for (int k=0;k<32;k++){
            float xv = xs[n*33+k];
            q = fmaf(xv, W1s[k*64+c], q);
            p = fmaf(xv, W2s[k*64+c], p);
        }
        g_Q1[(n0+n)*64 + c] = q;
        g_P2[(n0+n)*64 + c] = p;
    }
}

// ---------------- edge pass 1: stats of u = lrelu(z1) ------------------
__global__ void __launch_bounds__(256) k_edge_stats(const float* __restrict__ Wah_i){
    extern __shared__ float sm[];
    float*  xr  = sm;                       // 4224
    float2* de  = (float2*)(xr + 4224);     // 2048 float2
    float*  red = (float*)(de + 2048);      // 256

    int t  = threadIdx.x;
    int b  = blockIdx.y;
    int a0 = blockIdx.x*16;

    // zero g_sh1 accumulators for this step (consumed by previous node2)
    if (blockIdx.x == 0 && blockIdx.y == 0 && t < 32){
        g_sh1[t]=0.0; g_ssh1[t]=0.0;
    }

    for (int idx=t; idx<4096; idx+=256){
        int r = idx>>5, kk = idx&31;
        xr[r*33+kk] = g_x[b*4096 + idx];
    }
    __syncthreads();

    #pragma unroll
    for (int j=0;j<8;j++){
        int e  = t + 256*j;
        int as = e >> 7, p = e & 127;
        const float* xra = xr + (a0+as)*33;
        const float* xrp = xr + p*33;
        float s = 0.0f;
        #pragma unroll
        for (int kk=0;kk<31;kk++){
            float df = xrp[kk] - xra[kk] + 1e-12f;
            s = fmaf(df, df, s);
        }
        de[e] = make_float2(sqrtf(s), 1.0f - (xrp[31]-xra[31]));
    }
    __syncthreads();

    int k = t & 63, g = t >> 6;
    const float* P2b = g_P2 + (size_t)b*8192;
    float wdk = __ldg(Wah_i + 64*64 + k);
    float wik = __ldg(Wah_i + 65*64 + k);
    float q[16];
    #pragma unroll
    for (int as=0; as<16; as++) q[as] = __ldg(&g_Q1[(size_t)(b*128+a0+as)*64 + k]);

    float su = 0.0f, ssu = 0.0f;
    float pvn = __ldg(&P2b[g*64 + k]);
    #pragma unroll 2
    for (int m=0; m<32; m++){
        float pv = pvn;
        if (m < 31) pvn = __ldg(&P2b[(g + 4*(m+1))*64 + k]);
        int p = g + 4*m;
        #pragma unroll
        for (int as=0; as<16; as++){
            float2 e2 = de[as*128+p];
            float z = fmaf(e2.x, wdk, q[as] + pv);
            z = fmaf(e2.y, wik, z);
            float u = fmaxf(z, ALPHA*z);
            su += u; ssu = fmaf(u,u,ssu);
        }
    }
    red[g*64+k] = su;
    __syncthreads();
    if (g == 0)
        atomicAdd(&g_su[k], (double)(red[k]+red[64+k]+red[128+k]+red[192+k]));
    __syncthreads();
    red[g*64+k] = ssu;
    __syncthreads();
    if (g == 0)
        atomicAdd(&g_ssu[k], (double)(red[k]+red[64+k]+red[128+k]+red[192+k]));
}

// ---------------- edge pass 2: HMMA main (32 senders/CTA, 2 syncs/iter)
// byte offsets from 1024-aligned base
#define OFF_DE    0        // 32768 (32 x 128 float2)
#define OFF_Q1A   32768    // 8192  (32 x 64 f)
#define OFF_UHI   40960    // 18432 (rows 144B)  [xr transient alias]
#define OFF_ULO   59392    // 18432
#define OFF_WTHI  77824    // 4608 (32 rows x 144B)
#define OFF_WTLO  82432    // 4608
#define OFF_RED   87040    // 4096 (2 buffers x (256 sum + 256 sq))
#define OFF_BAF   91136    // 128
#define OFF_S1    91264    // 256
#define OFF_T1    91520    // 256
#define SMEM_MAIN_BYTES (1024 + 91776)
#define ROWB 144

__global__ void __launch_bounds__(256, 2) k_edge_main(
        const float* __restrict__ Wah_i,
        const float* __restrict__ Wa_i,  const float* __restrict__ ba_i,
        const float* __restrict__ geh_i, const float* __restrict__ beh_i){
    extern __shared__ char smraw[];
    char* A0 = (char*)(((uintptr_t)smraw + 1023) & ~(uintptr_t)1023);

    float2* de   = (float2*)(A0 + OFF_DE);
    float*  Q1a  = (float*)(A0 + OFF_Q1A);
    char*   uhi  = A0 + OFF_UHI;
    char*   ulo  = A0 + OFF_ULO;
    char*   wthi = A0 + OFF_WTHI;
    char*   wtlo = A0 + OFF_WTLO;
    float*  xr   = (float*)uhi;            // transient (16896B <= 18432B)
    float*  redb = (float*)(A0 + OFF_RED); // [2][512]
    float*  bafs = (float*)(A0 + OFF_BAF);
    float*  s1   = (float*)(A0 + OFF_S1);
    float*  t1   = (float*)(A0 + OFF_T1);

    int t    = threadIdx.x;
    int w    = t >> 5, lane = t & 31;
    int b    = blockIdx.y;
    int a0   = blockIdx.x*32;

    // --- prologue stage 1: xr, Q1a, BN1 scale/shift ---
    for (int idx=t; idx<4096; idx+=256){
        int r = idx>>5, kk = idx&31;
        xr[r*33+kk] = g_x[b*4096 + idx];
    }
    for (int idx=t; idx<2048; idx+=256)
        Q1a[idx] = g_Q1[(size_t)(b*128+a0)*64 + idx];
    if (t < 64){
        double m = g_su[t]/NE_D;
        double v = g_ssu[t]/NE_D - m*m;
        float s = geh_i[t] * rsqrtf((float)v + BNEPS);
        s1[t] = s; t1[t] = beh_i[t] - (float)m*s;
    }
    __syncthreads();

    // --- prologue stage 2: distances (32 senders), W split, bias fold ---
    #pragma unroll
    for (int j=0;j<16;j++){
        int e  = t + 256*j;                // 0..4095
        int as = e >> 7, p = e & 127;
        const float* xra = xr + (a0+as)*33;
        const float* xrp = xr + p*33;
        float s = 0.0f;
        #pragma unroll
        for (int kk=0;kk<31;kk++){
            float df = xrp[kk] - xra[kk] + 1e-12f;
            s = fmaf(df, df, s);
        }
        de[e] = make_float2(sqrtf(s), 1.0f - (xrp[31]-xra[31]));
    }
    for (int idx=t; idx<2048; idx+=256){
        int c = idx>>6, k = idx&63;
        float wv = s1[k]*Wa_i[k*32+c];
        __nv_bfloat16 hi = __float2bfloat16(wv);
        *(__nv_bfloat16*)(wthi + c*ROWB + k*2) = hi;
        *(__nv_bfloat16*)(wtlo + c*ROWB + k*2) =
            __float2bfloat16(wv - __bfloat162float(hi));
    }
    if (t < 32){
        float acc = ba_i[t];
        #pragma unroll
        for (int k=0;k<64;k++) acc = fmaf(t1[k], Wa_i[k*32+t], acc);
        bafs[t] = acc;
    }
    __syncthreads();   // xr dead; uhi/ulo free; wthi/wtlo/bafs ready

    // --- persistent B fragments (W^T hi+lo), per warp ---
    uint32_t bh[4][4][2], bl[4][4][2];
    {
        int li = lane & 15;
        uint32_t rsel = (uint32_t)((li & 7)*ROWB);
        uint32_t ksel = (uint32_t)((li >> 3)*16);
        #pragma unroll
        for (int kt=0; kt<4; kt++){
            #pragma unroll
            for (int nt=0; nt<4; nt++){
                uint32_t off = (uint32_t)(nt*8*ROWB) + rsel + (uint32_t)(kt*32) + ksel;
                ldmx2(bh[kt][nt], s2u(wthi) + off);
                ldmx2(bl[kt][nt], s2u(wtlo) + off);
            }
        }
    }
    int tc = lane & 3;
    float bias0[4], bias1[4];
    #pragma unroll
    for (int nt=0; nt<4; nt++){
        bias0[nt] = bafs[8*nt + 2*tc];
        bias1[nt] = bafs[8*nt + 2*tc + 1];
    }

    // phase-A per-thread constants
    int kp = lane;                         // k-pair 0..31
    float wd0 = __ldg(Wah_i + 64*64 + 2*kp), wd1 = __ldg(Wah_i + 64*64 + 2*kp + 1);
    float wi0 = __ldg(Wah_i + 65*64 + 2*kp), wi1 = __ldg(Wah_i + 65*64 + 2*kp + 1);
    const float2* P2b = (const float2*)(g_P2 + (size_t)b*8192);

    uint32_t aoff = (uint32_t)((w*16 + (lane & 15))*ROWB) + ((lane & 16) ? 16u : 0u);
    uint32_t uhiB = s2u(uhi), uloB = s2u(ulo);

    float vtot = 0.0f, ssvtot = 0.0f;      // t<32 only

    for (int as=0; as<32; as++){
        // ---- phase A: u -> bf16 hi/lo tiles ----
        {
            float2 q = *(const float2*)(Q1a + as*64 + 2*kp);
            #pragma unroll
            for (int j=0;j<16;j++){
                int p = w + 8*j;
                float2 pv = __ldg(&P2b[p*32 + kp]);
                float2 dd = de[as*128 + p];
                float z0 = fmaf(dd.x, wd0, q.x + pv.x); z0 = fmaf(dd.y, wi0, z0);
                float z1 = fmaf(dd.x, wd1, q.y + pv.y); z1 = fmaf(dd.y, wi1, z1);
                float u0 = fmaxf(z0, ALPHA*z0);
                float u1 = fmaxf(z1, ALPHA*z1);
                __nv_bfloat162 h2 = __floats2bfloat162_rn(u0, u1);
                float2 hf = __bfloat1622float2(h2);
                __nv_bfloat162 l2 = __floats2bfloat162_rn(u0 - hf.x, u1 - hf.y);
                *(__nv_bfloat162*)(uhi + p*ROWB + kp*4) = h2;
                *(__nv_bfloat162*)(ulo + p*ROWB + kp*4) = l2;
            }
        }
        // ---- drain previous iteration's reduction (overlaps phase A) ----
        if (as > 0 && t < 32){
            const float* rb0 = redb + ((as-1)&1)*512;
            float S = 0.0f, SS = 0.0f;
            #pragma unroll
            for (int j=0;j<8;j++){ S += rb0[j*32 + t]; SS += rb0[256 + j*32 + t]; }
            g_Sagg[(size_t)(b*128 + a0 + as - 1)*32 + t] = S;
            vtot += S; ssvtot += SS;
        }
        __syncthreads();   // u tiles ready; red[(as-1)&1] drained

        // ---- phase B: 3-pass bf16 HMMA, accumulate fp32 ----
        float C[4][4];
        #pragma unroll
        for (int nt=0;nt<4;nt++){
            C[nt][0]=0.f; C[nt][1]=0.f; C[nt][2]=0.f; C[nt][3]=0.f;
        }
        #pragma unroll
        for (int kt=0; kt<4; kt++){
            uint32_t ah[4], al[4];
            ldmx4(ah, uhiB + aoff + kt*32);
            ldmx4(al, uloB + aoff + kt*32);
            #pragma unroll
            for (int nt=0; nt<4; nt++){
                mma16816(C[nt], ah, bh[kt][nt]);
                mma16816(C[nt], ah, bl[kt][nt]);
                mma16816(C[nt], al, bh[kt][nt]);
            }
        }

        // ---- epilogue: bias + lrelu, row-sum + sq-sum per channel ----
        float* rb = redb + (as&1)*512;
        #pragma unroll
        for (int nt=0; nt<4; nt++){
            float y00 = C[nt][0] + bias0[nt];
            float y01 = C[nt][1] + bias1[nt];
            float y10 = C[nt][2] + bias0[nt];
            float y11 = C[nt][3] + bias1[nt];
            float v00 = fmaxf(y00, ALPHA*y00);
            float v01 = fmaxf(y01, ALPHA*y01);
            float v10 = fmaxf(y10, ALPHA*y10);
            float v11 = fmaxf(y11, ALPHA*y11);
            float cs0 = v00 + v10, cs1 = v01 + v11;
            float sq0 = fmaf(v00,v00, v10*v10);
            float sq1 = fmaf(v01,v01, v11*v11);
            #pragma unroll
            for (int off=4; off<32; off<<=1){
                cs0 += __shfl_xor_sync(0xFFFFFFFFu, cs0, off);
                cs1 += __shfl_xor_sync(0xFFFFFFFFu, cs1, off);
                sq0 += __shfl_xor_sync(0xFFFFFFFFu, sq0, off);
                sq1 += __shfl_xor_sync(0xFFFFFFFFu, sq1, off);
            }
            if (lane < 4){
                rb[w*32 + 8*nt + 2*tc]       = cs0;
                rb[w*32 + 8*nt + 2*tc + 1]   = cs1;
                rb[256 + w*32 + 8*nt + 2*tc]     = sq0;
                rb[256 + w*32 + 8*nt + 2*tc + 1] = sq1;
            }
        }
        __syncthreads();   // red[as&1] complete; u tiles consumed
    }

    // final drain (as=31)
    if (t < 32){
        const float* rb0 = redb + (31&1)*512;
        float S = 0.0f, SS = 0.0f;
        #pragma unroll
        for (int j=0;j<8;j++){ S += rb0[j*32 + t]; SS += rb0[256 + j*32 + t]; }
        g_Sagg[(size_t)(b*128 + a0 + 31)*32 + t] = S;
        vtot += S; ssvtot += SS;
        atomicAdd(&g_sv[t],  (double)vtot);
        atomicAdd(&g_ssv[t], (double)ssvtot);
    }
}

// ---------------- node layer 0 (staged, coalesced) ---------------------
__global__ void __launch_bounds__(128) k_node0(const float* __restrict__ Wn0_i,
                                               const float* __restrict__ bn0_i,
                                               const float* __restrict__ ge_i,
                                               const float* __restrict__ be_i){
    __shared__ float W[2048];
    __shared__ float sA[4096];
    __shared__ float sX[4096];
    __shared__ float s2[32], t2[32], bsh[32], ssum[32], sssum[32];
    int t = threadIdx.x;
    int row0 = blockIdx.x*128;
    if (t < 32){
        double m = g_sv[t]/NE_D;
        double v = g_ssv[t]/NE_D - m*m;
        float s = ge_i[t] * rsqrtf((float)v + BNEPS);
        s2[t] = s; t2[t] = be_i[t] - (float)m*s;
        bsh[t] = bn0_i[t]; ssum[t] = 0.0f; sssum[t] = 0.0f;
    }
    // zero g_su/g_ssu for next step's stats (main already consumed them)
    if (blockIdx.x == 0 && t >= 32 && t < 96){
        g_su[t-32] = 0.0; g_ssu[t-32] = 0.0;
    }
    for (int idx=t; idx<512; idx+=128)
        ((float4*)W)[idx] = ((const float4*)Wn0_i)[idx];
    for (int idx=t; idx<1024; idx+=128){
        ((float4*)sA)[idx] = ((const float4*)(g_Sagg + (size_t)row0*32))[idx];
        ((float4*)sX)[idx] = ((const float4*)(g_x    + (size_t)row0*32))[idx];
    }
    __syncthreads();

    float in[64];
    #pragma unroll
    for (int cc=0;cc<32;cc++){
        in[cc]    = fmaf(s2[cc], sA[t*32+cc], 128.0f*t2[cc]);
        in[32+cc] = sX[t*32+cc];
    }
    float z[32];
    #pragma unroll
    for (int cc=0;cc<32;cc++) z[cc] = bsh[cc];
    const float4* W4 = (const float4*)W;
    #pragma unroll
    for (int kk=0;kk<64;kk++){
        float xv = in[kk];
        #pragma unroll
        for (int j=0;j<8;j++){
            float4 wv = W4[kk*8+j];
            z[4*j+0] = fmaf(xv, wv.x, z[4*j+0]);
            z[4*j+1] = fmaf(xv, wv.y, z[4*j+1]);
            z[4*j+2] = fmaf(xv, wv.z, z[4*j+2]);
            z[4*j+3] = fmaf(xv, wv.w, z[4*j+3]);
        }
    }
    int lane = t & 31;
    #pragma unroll
    for (int cc=0;cc<32;cc++){
        float h = lrelu(z[cc]);
        sA[t*32+cc] = h;
        float v1 = h, v2 = h*h;
        #pragma unroll
        for (int off=16; off>0; off>>=1){
            v1 += __shfl_xor_sync(0xFFFFFFFFu, v1, off);
            v2 += __shfl_xor_sync(0xFFFFFFFFu, v2, off);
        }
        if (lane == 0){ atomicAdd(&ssum[cc], v1); atomicAdd(&sssum[cc], v2); }
    }
    __syncthreads();
    for (int idx=t; idx<1024; idx+=128)
        ((float4*)(g_h1 + (size_t)row0*32))[idx] = ((float4*)sA)[idx];
    if (t < 32){
        atomicAdd(&g_sh0[t], (double)ssum[t]);
        atomicAdd(&g_ssh0[t], (double)sssum[t]);
    }
}

// ---------------- node layer 1 -----------------------------------------
__global__ void __launch_bounds__(128) k_node1(const float* __restrict__ Wn_i,
                                               const float* __restrict__ bnn_i,
                                               const float* __restrict__ gn0,
                                               const float* __restrict__ bn0v){
    __shared__ float W[1024];
    __shared__ float sH[4096];
    __shared__ float s0[32], t0[32], bsh[32], ssum[32], sssum[32];
    int t = threadIdx.x;
    int row0 = blockIdx.x*128;
    if (t < 32){
        double m = g_sh0[t]/NT_D;
        double v = g_ssh0[t]/NT_D - m*m;
        float s = gn0[t] * rsqrtf((float)v + BNEPS);
        s0[t] = s; t0[t] = bn0v[t] - (float)m*s;
        bsh[t] = bnn_i[t]; ssum[t] = 0.0f; sssum[t] = 0.0f;
    }
    // zero g_sv/g_ssv for next step's main (node0 already consumed them)
    if (blockIdx.x == 0 && t >= 32 && t < 64){
        g_sv[t-32] = 0.0; g_ssv[t-32] = 0.0;
    }
    for (int idx=t; idx<256; idx+=128)
        ((float4*)W)[idx] = ((const float4*)Wn_i)[idx];
    for (int idx=t; idx<1024; idx+=128)
        ((float4*)sH)[idx] = ((const float4*)(g_h1 + (size_t)row0*32))[idx];
    __syncthreads();

    float hn[32];
    #pragma unroll
    for (int kk=0;kk<32;kk++) hn[kk] = fmaf(s0[kk], sH[t*32+kk], t0[kk]);
    float z[32];
    #pragma unroll
    for (int cc=0;cc<32;cc++) z[cc] = bsh[cc];
    const float4* W4 = (const float4*)W;
    #pragma unroll
    for (int kk=0;kk<32;kk++){
        float xv = hn[kk];
        #pragma unroll
        for (int j=0;j<8;j++){
            float4 wv = W4[kk*8+j];
            z[4*j+0] = fmaf(xv, wv.x, z[4*j+0]);
            z[4*j+1] = fmaf(xv, wv.y, z[4*j+1]);
            z[4*j+2] = fmaf(xv, wv.z, z[4*j+2]);
            z[4*j+3] = fmaf(xv, wv.w, z[4*j+3]);
        }
    }
    int lane = t & 31;
    #pragma unroll
    for (int cc=0;cc<32;cc++){
        float h = lrelu(z[cc]);
        sH[t*32+cc] = h;
        float v1 = h, v2 = h*h;
        #pragma unroll
        for (int off=16; off>0; off>>=1){
            v1 += __shfl_xor_sync(0xFFFFFFFFu, v1, off);
            v2 += __shfl_xor_sync(0xFFFFFFFFu, v2, off);
        }
        if (lane == 0){ atomicAdd(&ssum[cc], v1); atomicAdd(&sssum[cc], v2); }
    }
    __syncthreads();
    for (int idx=t; idx<1024; idx+=128)
        ((float4*)(g_h2 + (size_t)row0*32))[idx] = ((float4*)sH)[idx];
    if (t < 32){
        atomicAdd(&g_sh1[t], (double)ssum[t]);
        atomicAdd(&g_ssh1[t], (double)sssum[t]);
    }
}

// ---------------- node final: update linear + tanh (+fused pre) --------
__global__ void __launch_bounds__(128) k_node2(const float* __restrict__ Wu_i,
                                               const float* __restrict__ bu_i,
                                               const float* __restrict__ gn1,
                                               const float* __restrict__ bn1v,
                                               float* __restrict__ out,
                                               int is_last,
                                               const float* __restrict__ Wah_n,
                                               const float* __restrict__ bah_n){
    __shared__ float W[1024];
    __shared__ float sH[4096];
    __shared__ float W1s[2048];
    __shared__ float W2s[2048];
    __shared__ float bs[64];
    __shared__ float s0[32], t0[32], bsh[32];
    int t = threadIdx.x;
    int row0 = blockIdx.x*128;
    if (t < 32){
        double m = g_sh1[t]/NT_D;
        double v = g_ssh1[t]/NT_D - m*m;
        float s = gn1[t] * rsqrtf((float)v + BNEPS);
        s0[t] = s; t0[t] = bn1v[t] - (float)m*s;
        bsh[t] = bu_i[t];
    }
    // zero g_sh0/g_ssh0 for next step's node0 (node1 already consumed them)
    if (blockIdx.x == 0 && t >= 32 && t < 64){
        g_sh0[t-32] = 0.0; g_ssh0[t-32] = 0.0;
    }
    for (int idx=t; idx<256; idx+=128)
        ((float4*)W)[idx] = ((const float4*)Wu_i)[idx];
    for (int idx=t; idx<1024; idx+=128)
        ((float4*)sH)[idx] = ((const float4*)(g_h2 + (size_t)row0*32))[idx];
    if (!is_last){
        for (int idx=t; idx<2048; idx+=128){
            int k = idx>>6, c = idx&63;
            W1s[idx] = Wah_n[k*64 + c];
            W2s[idx] = Wah_n[(32+k)*64 + c];
        }
        if (t < 64) bs[t] = bah_n[t];
    }
    __syncthreads();

    float hn[32];
    #pragma unroll
    for (int kk=0;kk<32;kk++) hn[kk] = fmaf(s0[kk], sH[t*32+kk], t0[kk]);
    float z[32];
    #pragma unroll
    for (int cc=0;cc<32;cc++) z[cc] = bsh[cc];
    const float4* W4 = (const float4*)W;
    #pragma unroll
    for (int kk=0;kk<32;kk++){
        float xv = hn[kk];
        #pragma unroll
        for (int j=0;j<8;j++){
            float4 wv = W4[kk*8+j];
            z[4*j+0] = fmaf(xv, wv.x, z[4*j+0]);
            z[4*j+1] = fmaf(xv, wv.y, z[4*j+1]);
            z[4*j+2] = fmaf(xv, wv.z, z[4*j+2]);
            z[4*j+3] = fmaf(xv, wv.w, z[4*j+3]);
        }
    }
    __syncthreads();
    #pragma unroll
    for (int cc=0;cc<32;cc++) sH[t*32+cc] = tanhf(z[cc]);
    __syncthreads();
    for (int idx=t; idx<1024; idx+=128){
        float4 o4 = ((float4*)sH)[idx];
        ((float4*)(g_x + (size_t)row0*32))[idx] = o4;
        if (is_last) ((float4*)(out + (size_t)row0*32))[idx] = o4;
    }

    // ---- fused pre for next step: Q1/P2 of this block's 128 rows ----
    if (!is_last){
        int c = t & 63, ng = t >> 6;       // 2 groups of 64 channels
        for (int n=ng; n<128; n+=2){
            const float* xrow = sH + n*32;
            float q = bs[c], p = 0.0f;
            #pragma unroll
            for (int k=0;k<32;k++){
                float xv = xrow[k];
                q = fmaf(xv, W1s[k*64+c], q);
                p = fmaf(xv, W2s[k*64+c], p);
            }
            g_Q1[(size_t)(row0+n)*64 + c] = q;
            g_P2[(size_t)(row0+n)*64 + c] = p;
        }
    }
}

// ----------------------------------------------------------------------
extern "C" void kernel_launch(void* const* d_in, const int* in_sizes, int n_in,
                              void* d_out, int out_size){
    const float* x    = (const float*)d_in[0];
    const float* Wah  = (const float*)d_in[1];
    const float* bah  = (const float*)d_in[2];
    const float* Wa   = (const float*)d_in[3];
    const float* ba   = (const float*)d_in[4];
    const float* geh  = (const float*)d_in[5];
    const float* beh  = (const float*)d_in[6];
    const float* ge   = (const float*)d_in[7];
    const float* be   = (const float*)d_in[8];
    const float* Wn0  = (const float*)d_in[9];
    const float* bn0  = (const float*)d_in[10];
    const float* Wn   = (const float*)d_in[11];
    const float* bnn  = (const float*)d_in[12];
    const float* gn   = (const float*)d_in[13];
    const float* bnv  = (const float*)d_in[14];
    const float* Wu   = (const float*)d_in[15];
    const float* bu   = (const float*)d_in[16];
    float* out = (float*)d_out;

    const size_t SMEM_STATS = (4224 + 4096 + 256)*sizeof(float);   // 34304
    cudaFuncSetAttribute(k_edge_stats, cudaFuncAttributeMaxDynamicSharedMemorySize, (int)SMEM_STATS);
    cudaFuncSetAttribute(k_edge_main,  cudaFuncAttributeMaxDynamicSharedMemorySize, SMEM_MAIN_BYTES);

    k_pad<<<NT*HH/256, 256>>>(x);
    k_pre<<<128,256>>>(Wah, bah);

    for (int i=0; i<4; i++){
        int inx = (i < 3) ? (i+1) : 0;     // next-step weight index (unused if last)
        k_edge_stats<<<dim3(8,64),256,SMEM_STATS>>>(Wah + i*66*64);
        k_edge_main<<<dim3(4,64),256,SMEM_MAIN_BYTES>>>(Wah + i*66*64,
                                                        Wa + i*64*32, ba + i*32,
                                                        geh + i*64, beh + i*64);
        k_node0<<<64,128>>>(Wn0 + i*64*32, bn0 + i*32, ge + i*32, be + i*32);
        k_node1<<<64,128>>>(Wn + i*32*32, bnn + i*32, gn + (i*2+0)*32, bnv + (i*2+0)*32);
        k_node2<<<64,128>>>(Wu + i*32*32, bu + i*32, gn + (i*2+1)*32, bnv + (i*2+1)*32,
                            out, (i==3) ? 1 : 0,
                            Wah + inx*66*64, bah + inx*64);
    }
}

// round 16
// speedup vs baseline: 1.0684x; 1.0229x over previous
#include <cuda_runtime.h>
#include <cuda_bf16.h>
#include <math.h>
#include <stdint.h>

#define BB 64
#define NNODES 128
#define HH 32
#define HEc 64
#define OEc 32
#define NT (BB*NNODES)
#define ALPHA 0.1f
#define BNEPS 1e-5f
#define NBLK_EDGE 256u

static const double NE_D = 1048576.0;  // B*N*N edges
static const double NT_D = 8192.0;     // B*N nodes

// ----------------- device scratch (no allocs allowed) -----------------
__device__ __align__(16) float g_x[NT*HH];
__device__ __align__(16) float g_Q1[NT*HEc];
__device__ __align__(16) float g_P2[NT*HEc];
__device__ __align__(16) float g_Sagg[NT*OEc];
__device__ __align__(16) float g_h1[NT*HH];
__device__ __align__(16) float g_h2[NT*HH];
__device__ double g_su[HEc],  g_ssu[HEc];
__device__ double g_sv[OEc],  g_ssv[OEc];
__device__ double g_sh0[HH],  g_ssh0[HH];
__device__ double g_sh1[HH],  g_ssh1[HH];
__device__ unsigned int g_bar[8];

__device__ __forceinline__ float lrelu(float z){ return fmaxf(z, ALPHA*z); }

// ---------------- warp-MMA helpers (base ISA: sm_80+) -------------------
__device__ __forceinline__ uint32_t s2u(const void* p){
    return (uint32_t)__cvta_generic_to_shared(p);
}
__device__ __forceinline__ void ldmx4(uint32_t* r, uint32_t a){
    asm volatile("ldmatrix.sync.aligned.m8n8.x4.shared.b16 {%0,%1,%2,%3}, [%4];"
        : "=r"(r[0]),"=r"(r[1]),"=r"(r[2]),"=r"(r[3]) : "r"(a));
}
__device__ __forceinline__ void ldmx2(uint32_t* r, uint32_t a){
    asm volatile("ldmatrix.sync.aligned.m8n8.x2.shared.b16 {%0,%1}, [%2];"
        : "=r"(r[0]),"=r"(r[1]) : "r"(a));
}
__device__ __forceinline__ void mma16816(float* c, const uint32_t* a, const uint32_t* b){
    asm volatile("mma.sync.aligned.m16n8k16.row.col.f32.bf16.bf16.f32 "
        "{%0,%1,%2,%3}, {%4,%5,%6,%7}, {%8,%9}, {%0,%1,%2,%3};"
        : "+f"(c[0]),"+f"(c[1]),"+f"(c[2]),"+f"(c[3])
        : "r"(a[0]),"r"(a[1]),"r"(a[2]),"r"(a[3]), "r"(b[0]),"r"(b[1]));
}

// ----------------------------------------------------------------------
__global__ void k_pad(const float* __restrict__ xin){
    int i = blockIdx.x*256 + threadIdx.x;
    if (blockIdx.x == 0){
        int t = threadIdx.x;
        if (t < 64){ g_su[t]=0.0; g_ssu[t]=0.0; }
        if (t < 32){ g_sv[t]=0.0; g_ssv[t]=0.0;
                     g_sh0[t]=0.0; g_ssh0[t]=0.0;
                     g_sh1[t]=0.0; g_ssh1[t]=0.0; }
        if (t < 8) g_bar[t] = 0u;
    }
    if (i < NT*HH){
        int node = i >> 5, k = i & 31;
        g_x[i] = (k < 3) ? xin[node*3 + k] : 0.0f;
    }
}

// Q1 = x@Wah[0:32] + bah ; P2 = x@Wah[32:64]
__global__ void __launch_bounds__(256) k_pre(const float* __restrict__ Wah_i,
                                             const float* __restrict__ bah_i){
    __shared__ float xs[64*33];
    __shared__ float W1s[32*64];
    __shared__ float W2s[32*64];
    __shared__ float bs[64];
    int t = threadIdx.x;
    int n0 = blockIdx.x*64;
    for (int idx=t; idx<64*32; idx+=256){
        int n = idx>>5, k = idx&31;
        xs[n*33+k] = g_x[(n0+n)*32 + k];
    }
    for (int idx=t; idx<32*64; idx+=256){
        int k = idx>>6, c = idx&63;
        W1s[idx] = Wah_i[k*64 + c];
        W2s[idx] = Wah_i[(32+k)*64 + c];
    }
    if (t < 64) bs[t] = bah_i[t];
    __syncthreads();
    int c = t & 63, ng = t >> 6;
    for (int n=ng; n<64; n+=4){
        float q = bs[c], p = 0.0f;
        #pragma unroll
        for (int k=0;k<32;k++){
            float xv = xs[n*33+k];
            q = fmaf(xv, W1s[k*64+c], q);
            p = fmaf(xv, W2s[k*64+c], p);
        }
        g_Q1[(n0+n)*64 + c] = q;
        g_P2[(n0+n)*64 + c] = p;
    }
}

// ---- merged edge kernel: stats + grid barrier + fold + HMMA main ------
// byte offsets from 1024-aligned base
#define OFF_DE    0        // 32768 (32 x 128 float2)
#define OFF_Q1A   32768    // 8192  (32 x 64 f)
#define OFF_UHI   40960    // 18432 (rows 144B)  [xr transient alias]
#define OFF_ULO   59392    // 18432
#define OFF_WTHI  77824    // 4608 (32 rows x 144B)
#define OFF_WTLO  82432    // 4608
#define OFF_RED   87040    // 4096 (2 buffers x (256 sum + 256 sq))
#define OFF_BAF   91136    // 128
#define OFF_S1    91264    // 256
#define OFF_T1    91520    // 256
#define SMEM_MAIN_BYTES (1024 + 91776)
#define ROWB 144

__global__ void __launch_bounds__(256, 2) k_edge_main(
        const float* __restrict__ Wah_i,
        const float* __restrict__ Wa_i,  const float* __restrict__ ba_i,
        const float* __restrict__ geh_i, const float* __restrict__ beh_i,
        int step){
    extern __shared__ char smraw[];
    char* A0 = (char*)(((uintptr_t)smraw + 1023) & ~(uintptr_t)1023);

    float2* de   = (float2*)(A0 + OFF_DE);
    float*  Q1a  = (float*)(A0 + OFF_Q1A);
    char*   uhi  = A0 + OFF_UHI;
    char*   ulo  = A0 + OFF_ULO;
    char*   wthi = A0 + OFF_WTHI;
    char*   wtlo = A0 + OFF_WTLO;
    float*  xr   = (float*)uhi;            // transient (16896B <= 18432B)
    float*  redb = (float*)(A0 + OFF_RED); // [2][512]
    float*  bafs = (float*)(A0 + OFF_BAF);
    float*  s1   = (float*)(A0 + OFF_S1);
    float*  t1   = (float*)(A0 + OFF_T1);

    int t    = threadIdx.x;
    int w    = t >> 5, lane = t & 31;
    int b    = blockIdx.y;
    int a0   = blockIdx.x*32;

    // zero g_sh1 accumulators for this step (consumed by previous node2)
    if (blockIdx.x == 0 && blockIdx.y == 0 && t < 32){
        g_sh1[t]=0.0; g_ssh1[t]=0.0;
    }

    // --- prologue stage 1: xr, Q1a ---
    for (int idx=t; idx<4096; idx+=256){
        int r = idx>>5, kk = idx&31;
        xr[r*33+kk] = g_x[b*4096 + idx];
    }
    for (int idx=t; idx<2048; idx+=256)
        Q1a[idx] = g_Q1[(size_t)(b*128+a0)*64 + idx];
    __syncthreads();

    // --- prologue stage 2: distances (32 senders) ---
    #pragma unroll
    for (int j=0;j<16;j++){
        int e  = t + 256*j;                // 0..4095
        int as = e >> 7, p = e & 127;
        const float* xra = xr + (a0+as)*33;
        const float* xrp = xr + p*33;
        float s = 0.0f;
        #pragma unroll
        for (int kk=0;kk<31;kk++){
            float df = xrp[kk] - xra[kk] + 1e-12f;
            s = fmaf(df, df, s);
        }
        de[e] = make_float2(sqrtf(s), 1.0f - (xrp[31]-xra[31]));
    }
    __syncthreads();

    // --- stats phase: su/ssu of u = lrelu(z1) over this block's edges ---
    {
        int k = t & 63, g = t >> 6;
        const float* P2b = g_P2 + (size_t)b*8192;
        float wdk = __ldg(Wah_i + 64*64 + k);
        float wik = __ldg(Wah_i + 65*64 + k);
        float su = 0.0f, ssu = 0.0f;
        #pragma unroll
        for (int half=0; half<2; half++){
            float q[16];
            #pragma unroll
            for (int as=0; as<16; as++) q[as] = Q1a[(half*16+as)*64 + k];
            float pvn = __ldg(&P2b[g*64 + k]);
            #pragma unroll 2
            for (int m=0; m<32; m++){
                float pv = pvn;
                if (m < 31) pvn = __ldg(&P2b[(g + 4*(m+1))*64 + k]);
                int p = g + 4*m;
                #pragma unroll
                for (int as=0; as<16; as++){
                    float2 e2 = de[(half*16+as)*128 + p];
                    float z = fmaf(e2.x, wdk, q[as] + pv);
                    z = fmaf(e2.y, wik, z);
                    float u = fmaxf(z, ALPHA*z);
                    su += u; ssu = fmaf(u,u,ssu);
                }
            }
        }
        redb[g*64+k] = su;
        __syncthreads();
        if (g == 0)
            atomicAdd(&g_su[k], (double)(redb[k]+redb[64+k]+redb[128+k]+redb[192+k]));
        __syncthreads();
        redb[g*64+k] = ssu;
        __syncthreads();
        if (g == 0)
            atomicAdd(&g_ssu[k], (double)(redb[k]+redb[64+k]+redb[128+k]+redb[192+k]));
    }

    // --- grid barrier (all 256 CTAs co-resident: one wave) ---
    __threadfence();
    __syncthreads();
    if (t == 0){
        atomicAdd(&g_bar[step], 1u);
        volatile unsigned int* bp = &g_bar[step];
        while (*bp < NBLK_EDGE) __nanosleep(128);
        __threadfence();
    }
    __syncthreads();

    // --- fold: BN1 scale/shift, W split, bias ---
    if (t < 64){
        double m = g_su[t]/NE_D;
        double v = g_ssu[t]/NE_D - m*m;
        float s = geh_i[t] * rsqrtf((float)v + BNEPS);
        s1[t] = s; t1[t] = beh_i[t] - (float)m*s;
    }
    __syncthreads();
    for (int idx=t; idx<2048; idx+=256){
        int c = idx>>6, k = idx&63;
        float wv = s1[k]*Wa_i[k*32+c];
        __nv_bfloat16 hi = __float2bfloat16(wv);
        *(__nv_bfloat16*)(wthi + c*ROWB + k*2) = hi;
        *(__nv_bfloat16*)(wtlo + c*ROWB + k*2) =
            __float2bfloat16(wv - __bfloat162float(hi));
    }
    if (t < 32){
        float acc = ba_i[t];
        #pragma unroll
        for (int k=0;k<64;k++) acc = fmaf(t1[k], Wa_i[k*32+t], acc);
        bafs[t] = acc;
    }
    __syncthreads();

    // --- persistent B fragments (W^T hi+lo), per warp ---
    uint32_t bh[4][4][2], bl[4][4][2];
    {
        int li = lane & 15;
        uint32_t rsel = (uint32_t)((li & 7)*ROWB);
        uint32_t ksel = (uint32_t)((li >> 3)*16);
        #pragma unroll
        for (int kt=0; kt<4; kt++){
            #pragma unroll
            for (int nt=0; nt<4; nt++){
                uint32_t off = (uint32_t)(nt*8*ROWB) + rsel + (uint32_t)(kt*32) + ksel;
                ldmx2(bh[kt][nt], s2u(wthi) + off);
                ldmx2(bl[kt][nt], s2u(wtlo) + off);
            }
        }
    }
    int tc = lane & 3;
    float bias0[4], bias1[4];
    #pragma unroll
    for (int nt=0; nt<4; nt++){
        bias0[nt] = bafs[8*nt + 2*tc];
        bias1[nt] = bafs[8*nt + 2*tc + 1];
    }

    // phase-A per-thread constants
    int kp = lane;                         // k-pair 0..31
    float wd0 = __ldg(Wah_i + 64*64 + 2*kp), wd1 = __ldg(Wah_i + 64*64 + 2*kp + 1);
    float wi0 = __ldg(Wah_i + 65*64 + 2*kp), wi1 = __ldg(Wah_i + 65*64 + 2*kp + 1);
    const float2* P2b = (const float2*)(g_P2 + (size_t)b*8192);

    uint32_t aoff = (uint32_t)((w*16 + (lane & 15))*ROWB) + ((lane & 16) ? 16u : 0u);
    uint32_t uhiB = s2u(uhi), uloB = s2u(ulo);

    float vtot = 0.0f, ssvtot = 0.0f;      // t<32 only

    for (int as=0; as<32; as++){
        // ---- phase A: u -> bf16 hi/lo tiles ----
        {
            float2 q = *(const float2*)(Q1a + as*64 + 2*kp);
            #pragma unroll
            for (int j=0;j<16;j++){
                int p = w + 8*j;
                float2 pv = __ldg(&P2b[p*32 + kp]);
                float2 dd = de[as*128 + p];
                float z0 = fmaf(dd.x, wd0, q.x + pv.x); z0 = fmaf(dd.y, wi0, z0);
                float z1 = fmaf(dd.x, wd1, q.y + pv.y); z1 = fmaf(dd.y, wi1, z1);
                float u0 = fmaxf(z0, ALPHA*z0);
                float u1 = fmaxf(z1, ALPHA*z1);
                __nv_bfloat162 h2 = __floats2bfloat162_rn(u0, u1);
                float2 hf = __bfloat1622float2(h2);
                __nv_bfloat162 l2 = __floats2bfloat162_rn(u0 - hf.x, u1 - hf.y);
                *(__nv_bfloat162*)(uhi + p*ROWB + kp*4) = h2;
                *(__nv_bfloat162*)(ulo + p*ROWB + kp*4) = l2;
            }
        }
        // ---- drain previous iteration's reduction (overlaps phase A) ----
        if (as > 0 && t < 32){
            const float* rb0 = redb + ((as-1)&1)*512;
            float S = 0.0f, SS = 0.0f;
            #pragma unroll
            for (int j=0;j<8;j++){ S += rb0[j*32 + t]; SS += rb0[256 + j*32 + t]; }
            g_Sagg[(size_t)(b*128 + a0 + as - 1)*32 + t] = S;
            vtot += S; ssvtot += SS;
        }
        __syncthreads();   // u tiles ready; red[(as-1)&1] drained

        // ---- phase B: 3-pass bf16 HMMA, accumulate fp32 ----
        float C[4][4];
        #pragma unroll
        for (int nt=0;nt<4;nt++){
            C[nt][0]=0.f; C[nt][1]=0.f; C[nt][2]=0.f; C[nt][3]=0.f;
        }
        #pragma unroll
        for (int kt=0; kt<4; kt++){
            uint32_t ah[4], al[4];
            ldmx4(ah, uhiB + aoff + kt*32);
            ldmx4(al, uloB + aoff + kt*32);
            #pragma unroll
            for (int nt=0; nt<4; nt++){
                mma16816(C[nt], ah, bh[kt][nt]);
                mma16816(C[nt], ah, bl[kt][nt]);
                mma16816(C[nt], al, bh[kt][nt]);
            }
        }

        // ---- epilogue: bias + lrelu, row-sum + sq-sum per channel ----
        float* rb = redb + (as&1)*512;
        #pragma unroll
        for (int nt=0; nt<4; nt++){
            float y00 = C[nt][0] + bias0[nt];
            float y01 = C[nt][1] + bias1[nt];
            float y10 = C[nt][2] + bias0[nt];
            float y11 = C[nt][3] + bias1[nt];
            float v00 = fmaxf(y00, ALPHA*y00);
            float v01 = fmaxf(y01, ALPHA*y01);
            float v10 = fmaxf(y10, ALPHA*y10);
            float v11 = fmaxf(y11, ALPHA*y11);
            float cs0 = v00 + v10, cs1 = v01 + v11;
            float sq0 = fmaf(v00,v00, v10*v10);
            float sq1 = fmaf(v01,v01, v11*v11);
            #pragma unroll
            for (int off=4; off<32; off<<=1){
                cs0 += __shfl_xor_sync(0xFFFFFFFFu, cs0, off);
                cs1 += __shfl_xor_sync(0xFFFFFFFFu, cs1, off);
                sq0 += __shfl_xor_sync(0xFFFFFFFFu, sq0, off);
                sq1 += __shfl_xor_sync(0xFFFFFFFFu, sq1, off);
            }
            if (lane < 4){
                rb[w*32 + 8*nt + 2*tc]       = cs0;
                rb[w*32 + 8*nt + 2*tc + 1]   = cs1;
                rb[256 + w*32 + 8*nt + 2*tc]     = sq0;
                rb[256 + w*32 + 8*nt + 2*tc + 1] = sq1;
            }
        }
        __syncthreads();   // red[as&1] complete; u tiles consumed
    }

    // final drain (as=31)
    if (t < 32){
        const float* rb0 = redb + (31&1)*512;
        float S = 0.0f, SS = 0.0f;
        #pragma unroll
        for (int j=0;j<8;j++){ S += rb0[j*32 + t]; SS += rb0[256 + j*32 + t]; }
        g_Sagg[(size_t)(b*128 + a0 + 31)*32 + t] = S;
        vtot += S; ssvtot += SS;
        atomicAdd(&g_sv[t],  (double)vtot);
        atomicAdd(&g_ssv[t], (double)ssvtot);
    }
}

// ---------------- node layer 0 (staged, coalesced) ---------------------
__global__ void __launch_bounds__(128) k_node0(const float* __restrict__ Wn0_i,
                                               const float* __restrict__ bn0_i,
                                               const float* __restrict__ ge_i,
                                               const float* __restrict__ be_i){
    __shared__ float W[2048];
    __shared__ float sA[4096];
    __shared__ float sX[4096];
    __shared__ float s2[32], t2[32], bsh[32], ssum[32], sssum[32];
    int t = threadIdx.x;
    int row0 = blockIdx.x*128;
    if (t < 32){
        double m = g_sv[t]/NE_D;
        double v = g_ssv[t]/NE_D - m*m;
        float s = ge_i[t] * rsqrtf((float)v + BNEPS);
        s2[t] = s; t2[t] = be_i[t] - (float)m*s;
        bsh[t] = bn0_i[t]; ssum[t] = 0.0f; sssum[t] = 0.0f;
    }
    if (blockIdx.x == 0 && t >= 32 && t < 96){
        g_su[t-32] = 0.0; g_ssu[t-32] = 0.0;
    }
    for (int idx=t; idx<512; idx+=128)
        ((float4*)W)[idx] = ((const float4*)Wn0_i)[idx];
    for (int idx=t; idx<1024; idx+=128){
        ((float4*)sA)[idx] = ((const float4*)(g_Sagg + (size_t)row0*32))[idx];
        ((float4*)sX)[idx] = ((const float4*)(g_x    + (size_t)row0*32))[idx];
    }
    __syncthreads();

    float in[64];
    #pragma unroll
    for (int cc=0;cc<32;cc++){
        in[cc]    = fmaf(s2[cc], sA[t*32+cc], 128.0f*t2[cc]);
        in[32+cc] = sX[t*32+cc];
    }
    float z[32];
    #pragma unroll
    for (int cc=0;cc<32;cc++) z[cc] = bsh[cc];
    const float4* W4 = (const float4*)W;
    #pragma unroll
    for (int kk=0;kk<64;kk++){
        float xv = in[kk];
        #pragma unroll
        for (int j=0;j<8;j++){
            float4 wv = W4[kk*8+j];
            z[4*j+0] = fmaf(xv, wv.x, z[4*j+0]);
            z[4*j+1] = fmaf(xv, wv.y, z[4*j+1]);
            z[4*j+2] = fmaf(xv, wv.z, z[4*j+2]);
            z[4*j+3] = fmaf(xv, wv.w, z[4*j+3]);
        }
    }
    int lane = t & 31;
    #pragma unroll
    for (int cc=0;cc<32;cc++){
        float h = lrelu(z[cc]);
        sA[t*32+cc] = h;
        float v1 = h, v2 = h*h;
        #pragma unroll
        for (int off=16; off>0; off>>=1){
            v1 += __shfl_xor_sync(0xFFFFFFFFu, v1, off);
            v2 += __shfl_xor_sync(0xFFFFFFFFu, v2, off);
        }
        if (lane == 0){ atomicAdd(&ssum[cc], v1); atomicAdd(&sssum[cc], v2); }
    }
    __syncthreads();
    for (int idx=t; idx<1024; idx+=128)
        ((float4*)(g_h1 + (size_t)row0*32))[idx] = ((float4*)sA)[idx];
    if (t < 32){
        atomicAdd(&g_sh0[t], (double)ssum[t]);
        atomicAdd(&g_ssh0[t], (double)sssum[t]);
    }
}

// ---------------- node layer 1 -----------------------------------------
__global__ void __launch_bounds__(128) k_node1(const float* __restrict__ Wn_i,
                                               const float* __restrict__ bnn_i,
                                               const float* __restrict__ gn0,
                                               const float* __restrict__ bn0v){
    __shared__ float W[1024];
    __shared__ float sH[4096];
    __shared__ float s0[32], t0[32], bsh[32], ssum[32], sssum[32];
    int t = threadIdx.x;
    int row0 = blockIdx.x*128;
    if (t < 32){
        double m = g_sh0[t]/NT_D;
        double v = g_ssh0[t]/NT_D - m*m;
        float s = gn0[t] * rsqrtf((float)v + BNEPS);
        s0[t] = s; t0[t] = bn0v[t] - (float)m*s;
        bsh[t] = bnn_i[t]; ssum[t] = 0.0f; sssum[t] = 0.0f;
    }
    if (blockIdx.x == 0 && t >= 32 && t < 64){
        g_sv[t-32] = 0.0; g_ssv[t-32] = 0.0;
    }
    for (int idx=t; idx<256; idx+=128)
        ((float4*)W)[idx] = ((const float4*)Wn_i)[idx];
    for (int idx=t; idx<1024; idx+=128)
        ((float4*)sH)[idx] = ((const float4*)(g_h1 + (size_t)row0*32))[idx];
    __syncthreads();

    float hn[32];
    #pragma unroll
    for (int kk=0;kk<32;kk++) hn[kk] = fmaf(s0[kk], sH[t*32+kk], t0[kk]);
    float z[32];
    #pragma unroll
    for (int cc=0;cc<32;cc++) z[cc] = bsh[cc];
    const float4* W4 = (const float4*)W;
    #pragma unroll
    for (int kk=0;kk<32;kk++){
        float xv = hn[kk];
        #pragma unroll
        for (int j=0;j<8;j++){
            float4 wv = W4[kk*8+j];
            z[4*j+0] = fmaf(xv, wv.x, z[4*j+0]);
            z[4*j+1] = fmaf(xv, wv.y, z[4*j+1]);
            z[4*j+2] = fmaf(xv, wv.z, z[4*j+2]);
            z[4*j+3] = fmaf(xv, wv.w, z[4*j+3]);
        }
    }
    int lane = t & 31;
    #pragma unroll
    for (int cc=0;cc<32;cc++){
        float h = lrelu(z[cc]);
        sH[t*32+cc] = h;
        float v1 = h, v2 = h*h;
        #pragma unroll
        for (int off=16; off>0; off>>=1){
            v1 += __shfl_xor_sync(0xFFFFFFFFu, v1, off);
            v2 += __shfl_xor_sync(0xFFFFFFFFu, v2, off);
        }
        if (lane == 0){ atomicAdd(&ssum[cc], v1); atomicAdd(&sssum[cc], v2); }
    }
    __syncthreads();
    for (int idx=t; idx<1024; idx+=128)
        ((float4*)(g_h2 + (size_t)row0*32))[idx] = ((float4*)sH)[idx];
    if (t < 32){
        atomicAdd(&g_sh1[t], (double)ssum[t]);
        atomicAdd(&g_ssh1[t], (double)sssum[t]);
    }
}

// ---------------- node final: update linear + tanh ---------------------
__global__ void __launch_bounds__(128) k_node2(const float* __restrict__ Wu_i,
                                               const float* __restrict__ bu_i,
                                               const float* __restrict__ gn1,
                                               const float* __restrict__ bn1v,
                                               float* __restrict__ out,
                                               int is_last){
    __shared__ float W[1024];
    __shared__ float sH[4096];
    __shared__ float s0[32], t0[32], bsh[32];
    int t = threadIdx.x;
    int row0 = blockIdx.x*128;
    if (t < 32){
        double m = g_sh1[t]/NT_D;
        double v = g_ssh1[t]/NT_D - m*m;
        float s = gn1[t] * rsqrtf((float)v + BNEPS);
        s0[t] = s; t0[t] = bn1v[t] - (float)m*s;
        bsh[t] = bu_i[t];
    }
    if (blockIdx.x == 0 && t >= 32 && t < 64){
        g_sh0[t-32] = 0.0; g_ssh0[t-32] = 0.0;
    }
    for (int idx=t; idx<256; idx+=128)
        ((float4*)W)[idx] = ((const float4*)Wu_i)[idx];
    for (int idx=t; idx<1024; idx+=128)
        ((float4*)sH)[idx] = ((const float4*)(g_h2 + (size_t)row0*32))[idx];
    __syncthreads();

    float hn[32];
    #pragma unroll
    for (int kk=0;kk<32;kk++) hn[kk] = fmaf(s0[kk], sH[t*32+kk], t0[kk]);
    float z[32];
    #pragma unroll
    for (int cc=0;cc<32;cc++) z[cc] = bsh[cc];
    const float4* W4 = (const float4*)W;
    #pragma unroll
    for (int kk=0;kk<32;kk++){
        float xv = hn[kk];
        #pragma unroll
        for (int j=0;j<8;j++){
            float4 wv = W4[kk*8+j];
            z[4*j+0] = fmaf(xv, wv.x, z[4*j+0]);
            z[4*j+1] = fmaf(xv, wv.y, z[4*j+1]);
            z[4*j+2] = fmaf(xv, wv.z, z[4*j+2]);
            z[4*j+3] = fmaf(xv, wv.w, z[4*j+3]);
        }
    }
    #pragma unroll
    for (int cc=0;cc<32;cc++) sH[t*32+cc] = tanhf(z[cc]);
    __syncthreads();
    for (int idx=t; idx<1024; idx+=128){
        float4 o4 = ((float4*)sH)[idx];
        ((float4*)(g_x + (size_t)row0*32))[idx] = o4;
        if (is_last) ((float4*)(out + (size_t)row0*32))[idx] = o4;
    }
}

// ----------------------------------------------------------------------
extern "C" void kernel_launch(void* const* d_in, const int* in_sizes, int n_in,
                              void* d_out, int out_size){
    const float* x    = (const float*)d_in[0];
    const float* Wah  = (const float*)d_in[1];
    const float* bah  = (const float*)d_in[2];
    const float* Wa   = (const float*)d_in[3];
    const float* ba   = (const float*)d_in[4];
    const float* geh  = (const float*)d_in[5];
    const float* beh  = (const float*)d_in[6];
    const float* ge   = (const float*)d_in[7];
    const float* be   = (const float*)d_in[8];
    const float* Wn0  = (const float*)d_in[9];
    const float* bn0  = (const float*)d_in[10];
    const float* Wn   = (const float*)d_in[11];
    const float* bnn  = (const float*)d_in[12];
    const float* gn   = (const float*)d_in[13];
    const float* bnv  = (const float*)d_in[14];
    const float* Wu   = (const float*)d_in[15];
    const float* bu   = (const float*)d_in[16];
    float* out = (float*)d_out;

    cudaFuncSetAttribute(k_edge_main, cudaFuncAttributeMaxDynamicSharedMemorySize, SMEM_MAIN_BYTES);

    k_pad<<<NT*HH/256, 256>>>(x);

    for (int i=0; i<4; i++){
        k_pre<<<128,256>>>(Wah + i*66*64, bah + i*64);
        k_edge_main<<<dim3(4,64),256,SMEM_MAIN_BYTES>>>(Wah + i*66*64,
                                                        Wa + i*64*32, ba + i*32,
                                                        geh + i*64, beh + i*64, i);
        k_node0<<<64,128>>>(Wn0 + i*64*32, bn0 + i*32, ge + i*32, be + i*32);
        k_node1<<<64,128>>>(Wn + i*32*32, bnn + i*32, gn + (i*2+0)*32, bnv + (i*2+0)*32);
        k_node2<<<64,128>>>(Wu + i*32*32, bu + i*32, gn + (i*2+1)*32, bnv + (i*2+1)*32,
                            out, (i==3) ? 1 : 0);
    }
}

// round 17
// speedup vs baseline: 1.1364x; 1.0636x over previous
#include <cuda_runtime.h>
#include <cuda_bf16.h>
#include <math.h>
#include <stdint.h>

#define BB 64
#define NNODES 128
#define HH 32
#define HEc 64
#define OEc 32
#define NT (BB*NNODES)
#define ALPHA 0.1f
#define BNEPS 1e-5f
#define NBLK_EDGE 256u
#define NBLK_NODE 64u

static const double NE_D = 1048576.0;  // B*N*N edges
static const double NT_D = 8192.0;     // B*N nodes

// ----------------- device scratch (no allocs allowed) -----------------
__device__ __align__(16) float g_x[NT*HH];
__device__ __align__(16) float g_Q1[NT*HEc];
__device__ __align__(16) float g_P2[NT*HEc];
__device__ __align__(16) float g_Sagg[NT*OEc];
__device__ double g_su[HEc],  g_ssu[HEc];
__device__ double g_sv[OEc],  g_ssv[OEc];
__device__ double g_sh0[HH],  g_ssh0[HH];
__device__ double g_sh1[HH],  g_ssh1[HH];
__device__ unsigned int g_bar[16];

__device__ __forceinline__ float lrelu(float z){ return fmaxf(z, ALPHA*z); }

// ---------------- warp-MMA helpers (base ISA: sm_80+) -------------------
__device__ __forceinline__ uint32_t s2u(const void* p){
    return (uint32_t)__cvta_generic_to_shared(p);
}
__device__ __forceinline__ void ldmx4(uint32_t* r, uint32_t a){
    asm volatile("ldmatrix.sync.aligned.m8n8.x4.shared.b16 {%0,%1,%2,%3}, [%4];"
        : "=r"(r[0]),"=r"(r[1]),"=r"(r[2]),"=r"(r[3]) : "r"(a));
}
__device__ __forceinline__ void ldmx2(uint32_t* r, uint32_t a){
    asm volatile("ldmatrix.sync.aligned.m8n8.x2.shared.b16 {%0,%1}, [%2];"
        : "=r"(r[0]),"=r"(r[1]) : "r"(a));
}
__device__ __forceinline__ void mma16816(float* c, const uint32_t* a, const uint32_t* b){
    asm volatile("mma.sync.aligned.m16n8k16.row.col.f32.bf16.bf16.f32 "
        "{%0,%1,%2,%3}, {%4,%5,%6,%7}, {%8,%9}, {%0,%1,%2,%3};"
        : "+f"(c[0]),"+f"(c[1]),"+f"(c[2]),"+f"(c[3])
        : "r"(a[0]),"r"(a[1]),"r"(a[2]),"r"(a[3]), "r"(b[0]),"r"(b[1]));
}

// ----------------------------------------------------------------------
__global__ void k_pad(const float* __restrict__ xin){
    int i = blockIdx.x*256 + threadIdx.x;
    if (blockIdx.x == 0){
        int t = threadIdx.x;
        if (t < 64){ g_su[t]=0.0; g_ssu[t]=0.0; }
        if (t < 32){ g_sv[t]=0.0; g_ssv[t]=0.0;
                     g_sh0[t]=0.0; g_ssh0[t]=0.0;
                     g_sh1[t]=0.0; g_ssh1[t]=0.0; }
        if (t < 16) g_bar[t] = 0u;
    }
    if (i < NT*HH){
        int node = i >> 5, k = i & 31;
        g_x[i] = (k < 3) ? xin[node*3 + k] : 0.0f;
    }
}

// Q1 = x@Wah[0:32] + bah ; P2 = x@Wah[32:64]
__global__ void __launch_bounds__(256) k_pre(const float* __restrict__ Wah_i,
                                             const float* __restrict__ bah_i){
    __shared__ float xs[64*33];
    __shared__ float W1s[32*64];
    __shared__ float W2s[32*64];
    __shared__ float bs[64];
    int t = threadIdx.x;
    int n0 = blockIdx.x*64;
    for (int idx=t; idx<64*32; idx+=256){
        int n = idx>>5, k = idx&31;
        xs[n*33+k] = g_x[(n0+n)*32 + k];
    }
    for (int idx=t; idx<32*64; idx+=256){
        int k = idx>>6, c = idx&63;
        W1s[idx] = Wah_i[k*64 + c];
        W2s[idx] = Wah_i[(32+k)*64 + c];
    }
    if (t < 64) bs[t] = bah_i[t];
    __syncthreads();
    int c = t & 63, ng = t >> 6;
    for (int n=ng; n<64; n+=4){
        float q = bs[c], p = 0.0f;
        #pragma unroll
        for (int k=0;k<32;k++){
            float xv = xs[n*33+k];
            q = fmaf(xv, W1s[k*64+c], q);
            p = fmaf(xv, W2s[k*64+c], p);
        }
        g_Q1[(n0+n)*64 + c] = q;
        g_P2[(n0+n)*64 + c] = p;
    }
}

// ---- merged edge kernel: stats + grid barrier + fold + HMMA main ------
#define OFF_DE    0        // 32768 (32 x 128 float2)
#define OFF_Q1A   32768    // 8192  (32 x 64 f)
#define OFF_UHI   40960    // 18432 (rows 144B)  [xr transient alias]
#define OFF_ULO   59392    // 18432
#define OFF_WTHI  77824    // 4608 (32 rows x 144B)
#define OFF_WTLO  82432    // 4608
#define OFF_RED   87040    // 4096 (2 buffers x (256 sum + 256 sq))
#define OFF_BAF   91136    // 128
#define OFF_S1    91264    // 256
#define OFF_T1    91520    // 256
#define SMEM_MAIN_BYTES (1024 + 91776)
#define ROWB 144

__global__ void __launch_bounds__(256, 2) k_edge_main(
        const float* __restrict__ Wah_i,
        const float* __restrict__ Wa_i,  const float* __restrict__ ba_i,
        const float* __restrict__ geh_i, const float* __restrict__ beh_i,
        int step){
    extern __shared__ char smraw[];
    char* A0 = (char*)(((uintptr_t)smraw + 1023) & ~(uintptr_t)1023);

    float2* de   = (float2*)(A0 + OFF_DE);
    float*  Q1a  = (float*)(A0 + OFF_Q1A);
    char*   uhi  = A0 + OFF_UHI;
    char*   ulo  = A0 + OFF_ULO;
    char*   wthi = A0 + OFF_WTHI;
    char*   wtlo = A0 + OFF_WTLO;
    float*  xr   = (float*)uhi;
    float*  redb = (float*)(A0 + OFF_RED);
    float*  bafs = (float*)(A0 + OFF_BAF);
    float*  s1   = (float*)(A0 + OFF_S1);
    float*  t1   = (float*)(A0 + OFF_T1);

    int t    = threadIdx.x;
    int w    = t >> 5, lane = t & 31;
    int b    = blockIdx.y;
    int a0   = blockIdx.x*32;

    if (blockIdx.x == 0 && blockIdx.y == 0 && t < 32){
        g_sh1[t]=0.0; g_ssh1[t]=0.0;
    }

    for (int idx=t; idx<4096; idx+=256){
        int r = idx>>5, kk = idx&31;
        xr[r*33+kk] = g_x[b*4096 + idx];
    }
    for (int idx=t; idx<2048; idx+=256)
        Q1a[idx] = g_Q1[(size_t)(b*128+a0)*64 + idx];
    __syncthreads();

    #pragma unroll
    for (int j=0;j<16;j++){
        int e  = t + 256*j;
        int as = e >> 7, p = e & 127;
        const float* xra = xr + (a0+as)*33;
        const float* xrp = xr + p*33;
        float s = 0.0f;
        #pragma unroll
        for (int kk=0;kk<31;kk++){
            float df = xrp[kk] - xra[kk] + 1e-12f;
            s = fmaf(df, df, s);
        }
        de[e] = make_float2(sqrtf(s), 1.0f - (xrp[31]-xra[31]));
    }
    __syncthreads();

    {
        int k = t & 63, g = t >> 6;
        const float* P2b = g_P2 + (size_t)b*8192;
        float wdk = __ldg(Wah_i + 64*64 + k);
        float wik = __ldg(Wah_i + 65*64 + k);
        float su = 0.0f, ssu = 0.0f;
        #pragma unroll
        for (int half=0; half<2; half++){
            float q[16];
            #pragma unroll
            for (int as=0; as<16; as++) q[as] = Q1a[(half*16+as)*64 + k];
            float pvn = __ldg(&P2b[g*64 + k]);
            #pragma unroll 2
            for (int m=0; m<32; m++){
                float pv = pvn;
                if (m < 31) pvn = __ldg(&P2b[(g + 4*(m+1))*64 + k]);
                int p = g + 4*m;
                #pragma unroll
                for (int as=0; as<16; as++){
                    float2 e2 = de[(half*16+as)*128 + p];
                    float z = fmaf(e2.x, wdk, q[as] + pv);
                    z = fmaf(e2.y, wik, z);
                    float u = fmaxf(z, ALPHA*z);
                    su += u; ssu = fmaf(u,u,ssu);
                }
            }
        }
        redb[g*64+k] = su;
        __syncthreads();
        if (g == 0)
            atomicAdd(&g_su[k], (double)(redb[k]+redb[64+k]+redb[128+k]+redb[192+k]));
        __syncthreads();
        redb[g*64+k] = ssu;
        __syncthreads();
        if (g == 0)
            atomicAdd(&g_ssu[k], (double)(redb[k]+redb[64+k]+redb[128+k]+redb[192+k]));
    }

    __threadfence();
    __syncthreads();
    if (t == 0){
        atomicAdd(&g_bar[step], 1u);
        volatile unsigned int* bp = &g_bar[step];
        while (*bp < NBLK_EDGE) __nanosleep(128);
        __threadfence();
    }
    __syncthreads();

    if (t < 64){
        double m = g_su[t]/NE_D;
        double v = g_ssu[t]/NE_D - m*m;
        float s = geh_i[t] * rsqrtf((float)v + BNEPS);
        s1[t] = s; t1[t] = beh_i[t] - (float)m*s;
    }
    __syncthreads();
    for (int idx=t; idx<2048; idx+=256){
        int c = idx>>6, k = idx&63;
        float wv = s1[k]*Wa_i[k*32+c];
        __nv_bfloat16 hi = __float2bfloat16(wv);
        *(__nv_bfloat16*)(wthi + c*ROWB + k*2) = hi;
        *(__nv_bfloat16*)(wtlo + c*ROWB + k*2) =
            __float2bfloat16(wv - __bfloat162float(hi));
    }
    if (t < 32){
        float acc = ba_i[t];
        #pragma unroll
        for (int k=0;k<64;k++) acc = fmaf(t1[k], Wa_i[k*32+t], acc);
        bafs[t] = acc;
    }
    __syncthreads();

    uint32_t bh[4][4][2], bl[4][4][2];
    {
        int li = lane & 15;
        uint32_t rsel = (uint32_t)((li & 7)*ROWB);
        uint32_t ksel = (uint32_t)((li >> 3)*16);
        #pragma unroll
        for (int kt=0; kt<4; kt++){
            #pragma unroll
            for (int nt=0; nt<4; nt++){
                uint32_t off = (uint32_t)(nt*8*ROWB) + rsel + (uint32_t)(kt*32) + ksel;
                ldmx2(bh[kt][nt], s2u(wthi) + off);
                ldmx2(bl[kt][nt], s2u(wtlo) + off);
            }
        }
    }
    int tc = lane & 3;
    float bias0[4], bias1[4];
    #pragma unroll
    for (int nt=0; nt<4; nt++){
        bias0[nt] = bafs[8*nt + 2*tc];
        bias1[nt] = bafs[8*nt + 2*tc + 1];
    }

    int kp = lane;
    float wd0 = __ldg(Wah_i + 64*64 + 2*kp), wd1 = __ldg(Wah_i + 64*64 + 2*kp + 1);
    float wi0 = __ldg(Wah_i + 65*64 + 2*kp), wi1 = __ldg(Wah_i + 65*64 + 2*kp + 1);
    const float2* P2b = (const float2*)(g_P2 + (size_t)b*8192);

    uint32_t aoff = (uint32_t)((w*16 + (lane & 15))*ROWB) + ((lane & 16) ? 16u : 0u);
    uint32_t uhiB = s2u(uhi), uloB = s2u(ulo);

    float vtot = 0.0f, ssvtot = 0.0f;

    for (int as=0; as<32; as++){
        {
            float2 q = *(const float2*)(Q1a + as*64 + 2*kp);
            #pragma unroll
            for (int j=0;j<16;j++){
                int p = w + 8*j;
                float2 pv = __ldg(&P2b[p*32 + kp]);
                float2 dd = de[as*128 + p];
                float z0 = fmaf(dd.x, wd0, q.x + pv.x); z0 = fmaf(dd.y, wi0, z0);
                float z1 = fmaf(dd.x, wd1, q.y + pv.y); z1 = fmaf(dd.y, wi1, z1);
                float u0 = fmaxf(z0, ALPHA*z0);
                float u1 = fmaxf(z1, ALPHA*z1);
                __nv_bfloat162 h2 = __floats2bfloat162_rn(u0, u1);
                float2 hf = __bfloat1622float2(h2);
                __nv_bfloat162 l2 = __floats2bfloat162_rn(u0 - hf.x, u1 - hf.y);
                *(__nv_bfloat162*)(uhi + p*ROWB + kp*4) = h2;
                *(__nv_bfloat162*)(ulo + p*ROWB + kp*4) = l2;
            }
        }
        if (as > 0 && t < 32){
            const float* rb0 = redb + ((as-1)&1)*512;
            float S = 0.0f, SS = 0.0f;
            #pragma unroll
            for (int j=0;j<8;j++){ S += rb0[j*32 + t]; SS += rb0[256 + j*32 + t]; }
            g_Sagg[(size_t)(b*128 + a0 + as - 1)*32 + t] = S;
            vtot += S; ssvtot += SS;
        }
        __syncthreads();

        float C[4][4];
        #pragma unroll
        for (int nt=0;nt<4;nt++){
            C[nt][0]=0.f; C[nt][1]=0.f; C[nt][2]=0.f; C[nt][3]=0.f;
        }
        #pragma unroll
        for (int kt=0; kt<4; kt++){
            uint32_t ah[4], al[4];
            ldmx4(ah, uhiB + aoff + kt*32);
            ldmx4(al, uloB + aoff + kt*32);
            #pragma unroll
            for (int nt=0; nt<4; nt++){
                mma16816(C[nt], ah, bh[kt][nt]);
                mma16816(C[nt], ah, bl[kt][nt]);
                mma16816(C[nt], al, bh[kt][nt]);
            }
        }

        float* rb = redb + (as&1)*512;
        #pragma unroll
        for (int nt=0; nt<4; nt++){
            float y00 = C[nt][0] + bias0[nt];
            float y01 = C[nt][1] + bias1[nt];
            float y10 = C[nt][2] + bias0[nt];
            float y11 = C[nt][3] + bias1[nt];
            float v00 = fmaxf(y00, ALPHA*y00);
            float v01 = fmaxf(y01, ALPHA*y01);
            float v10 = fmaxf(y10, ALPHA*y10);
            float v11 = fmaxf(y11, ALPHA*y11);
            float cs0 = v00 + v10, cs1 = v01 + v11;
            float sq0 = fmaf(v00,v00, v10*v10);
            float sq1 = fmaf(v01,v01, v11*v11);
            #pragma unroll
            for (int off=4; off<32; off<<=1){
                cs0 += __shfl_xor_sync(0xFFFFFFFFu, cs0, off);
                cs1 += __shfl_xor_sync(0xFFFFFFFFu, cs1, off);
                sq0 += __shfl_xor_sync(0xFFFFFFFFu, sq0, off);
                sq1 += __shfl_xor_sync(0xFFFFFFFFu, sq1, off);
            }
            if (lane < 4){
                rb[w*32 + 8*nt + 2*tc]       = cs0;
                rb[w*32 + 8*nt + 2*tc + 1]   = cs1;
                rb[256 + w*32 + 8*nt + 2*tc]     = sq0;
                rb[256 + w*32 + 8*nt + 2*tc + 1] = sq1;
            }
        }
        __syncthreads();
    }

    if (t < 32){
        const float* rb0 = redb + (31&1)*512;
        float S = 0.0f, SS = 0.0f;
        #pragma unroll
        for (int j=0;j<8;j++){ S += rb0[j*32 + t]; SS += rb0[256 + j*32 + t]; }
        g_Sagg[(size_t)(b*128 + a0 + 31)*32 + t] = S;
        vtot += S; ssvtot += SS;
        atomicAdd(&g_sv[t],  (double)vtot);
        atomicAdd(&g_ssv[t], (double)ssvtot);
    }
}

// ---------------- merged node kernel: 3 layers + 2 grid barriers -------
// dynamic smem layout (floats): W0 2048 | W1 1024 | Wu 1024 | bufA 4096 |
//   bufB 4096 | sc 32 | sh 32 | bb 32 | red 256
#define NOF_W0   0
#define NOF_W1   2048
#define NOF_WU   3072
#define NOF_BA   4096
#define NOF_BB   8192
#define NOF_SC   12288
#define NOF_SH   12320
#define NOF_BBI  12352
#define NOF_RED  12384
#define SMEM_NODE_BYTES ((12384 + 256)*4)

__global__ void __launch_bounds__(128) k_nodes(
        const float* __restrict__ Wn0_i, const float* __restrict__ bn0_i,
        const float* __restrict__ ge_i,  const float* __restrict__ be_i,
        const float* __restrict__ Wn_i,  const float* __restrict__ bnn_i,
        const float* __restrict__ gn0,   const float* __restrict__ bn0v,
        const float* __restrict__ Wu_i,  const float* __restrict__ bu_i,
        const float* __restrict__ gn1,   const float* __restrict__ bn1v,
        float* __restrict__ out, int is_last, int step){
    extern __shared__ float sm[];
    float* W0   = sm + NOF_W0;
    float* W1   = sm + NOF_W1;
    float* Wu   = sm + NOF_WU;
    float* bufA = sm + NOF_BA;
    float* bufB = sm + NOF_BB;
    float* sc   = sm + NOF_SC;
    float* sh   = sm + NOF_SH;
    float* bb   = sm + NOF_BBI;
    float* red  = sm + NOF_RED;

    int t = threadIdx.x;
    int row0 = blockIdx.x*128;
    int c = t & 31, g = t >> 5;

    // ---- stage all weights + inputs; fold BN2(edge) ----
    for (int idx=t; idx<512; idx+=128)
        ((float4*)W0)[idx] = ((const float4*)Wn0_i)[idx];
    for (int idx=t; idx<256; idx+=128){
        ((float4*)W1)[idx] = ((const float4*)Wn_i)[idx];
        ((float4*)Wu)[idx] = ((const float4*)Wu_i)[idx];
    }
    for (int idx=t; idx<1024; idx+=128){
        ((float4*)bufA)[idx] = ((const float4*)(g_Sagg + (size_t)row0*32))[idx];
        ((float4*)bufB)[idx] = ((const float4*)(g_x    + (size_t)row0*32))[idx];
    }
    if (t < 32){
        double m = g_sv[t]/NE_D;
        double v = g_ssv[t]/NE_D - m*m;
        float s = ge_i[t] * rsqrtf((float)v + BNEPS);
        sc[t] = s; sh[t] = be_i[t] - (float)m*s;
        bb[t] = bn0_i[t];
    }
    // zero g_su for next step's edge stats (already consumed)
    if (blockIdx.x == 0 && t >= 32 && t < 96){
        g_su[t-32] = 0.0; g_ssu[t-32] = 0.0;
    }
    __syncthreads();

    // ---- phase 0: layer0 GEMM (64->32) ----
    {
        float in[64];
        #pragma unroll
        for (int cc=0;cc<32;cc++){
            in[cc]    = fmaf(sc[cc], bufA[t*32+cc], 128.0f*sh[cc]);
            in[32+cc] = bufB[t*32+cc];
        }
        float z[32];
        #pragma unroll
        for (int cc=0;cc<32;cc++) z[cc] = bb[cc];
        const float4* W4 = (const float4*)W0;
        #pragma unroll
        for (int kk=0;kk<64;kk++){
            float xv = in[kk];
            #pragma unroll
            for (int j=0;j<8;j++){
                float4 wv = W4[kk*8+j];
                z[4*j+0] = fmaf(xv, wv.x, z[4*j+0]);
                z[4*j+1] = fmaf(xv, wv.y, z[4*j+1]);
                z[4*j+2] = fmaf(xv, wv.z, z[4*j+2]);
                z[4*j+3] = fmaf(xv, wv.w, z[4*j+3]);
            }
        }
        #pragma unroll
        for (int cc=0;cc<32;cc++) bufA[t*32+cc] = lrelu(z[cc]);
    }
    __syncthreads();
    // channel reduction (conflict-free)
    {
        float S = 0.0f, SS = 0.0f;
        #pragma unroll
        for (int r=0;r<32;r++){
            float h = bufA[(g*32+r)*32 + c];
            S += h; SS = fmaf(h,h,SS);
        }
        red[g*32+c] = S; red[128+g*32+c] = SS;
    }
    __syncthreads();
    if (t < 32){
        atomicAdd(&g_sh0[t],  (double)(red[t]+red[32+t]+red[64+t]+red[96+t]));
        atomicAdd(&g_ssh0[t], (double)(red[128+t]+red[160+t]+red[192+t]+red[224+t]));
    }

    // ---- grid barrier A ----
    __threadfence();
    __syncthreads();
    if (t == 0){
        int slot = 4 + 2*step;
        atomicAdd(&g_bar[slot], 1u);
        volatile unsigned int* bp = &g_bar[slot];
        while (*bp < NBLK_NODE) __nanosleep(64);
        __threadfence();
    }
    __syncthreads();

    // ---- phase 1: BN(h0) fold + layer1 GEMM (32->32) ----
    if (t < 32){
        double m = g_sh0[t]/NT_D;
        double v = g_ssh0[t]/NT_D - m*m;
        float s = gn0[t] * rsqrtf((float)v + BNEPS);
        sc[t] = s; sh[t] = bn0v[t] - (float)m*s;
        bb[t] = bnn_i[t];
    }
    // zero g_sv for next step's edge main (consumed before barrier A)
    if (blockIdx.x == 0 && t >= 32 && t < 64){
        g_sv[t-32] = 0.0; g_ssv[t-32] = 0.0;
    }
    __syncthreads();
    {
        float hn[32];
        #pragma unroll
        for (int kk=0;kk<32;kk++) hn[kk] = fmaf(sc[kk], bufA[t*32+kk], sh[kk]);
        float z[32];
        #pragma unroll
        for (int cc=0;cc<32;cc++) z[cc] = bb[cc];
        const float4* W4 = (const float4*)W1;
        #pragma unroll
        for (int kk=0;kk<32;kk++){
            float xv = hn[kk];
            #pragma unroll
            for (int j=0;j<8;j++){
                float4 wv = W4[kk*8+j];
                z[4*j+0] = fmaf(xv, wv.x, z[4*j+0]);
                z[4*j+1] = fmaf(xv, wv.y, z[4*j+1]);
                z[4*j+2] = fmaf(xv, wv.z, z[4*j+2]);
                z[4*j+3] = fmaf(xv, wv.w, z[4*j+3]);
            }
        }
        __syncthreads();   // all reads of bufA(h0) done before overwrite
        #pragma unroll
        for (int cc=0;cc<32;cc++) bufA[t*32+cc] = lrelu(z[cc]);
    }
    __syncthreads();
    {
        float S = 0.0f, SS = 0.0f;
        #pragma unroll
        for (int r=0;r<32;r++){
            float h = bufA[(g*32+r)*32 + c];
            S += h; SS = fmaf(h,h,SS);
        }
        red[g*32+c] = S; red[128+g*32+c] = SS;
    }
    __syncthreads();
    if (t < 32){
        atomicAdd(&g_sh1[t],  (double)(red[t]+red[32+t]+red[64+t]+red[96+t]));
        atomicAdd(&g_ssh1[t], (double)(red[128+t]+red[160+t]+red[192+t]+red[224+t]));
    }

    // ---- grid barrier B ----
    __threadfence();
    __syncthreads();
    if (t == 0){
        int slot = 5 + 2*step;
        atomicAdd(&g_bar[slot], 1u);
        volatile unsigned int* bp = &g_bar[slot];
        while (*bp < NBLK_NODE) __nanosleep(64);
        __threadfence();
    }
    __syncthreads();

    // ---- phase 2: BN(h1) fold + update linear + tanh ----
    if (t < 32){
        double m = g_sh1[t]/NT_D;
        double v = g_ssh1[t]/NT_D - m*m;
        float s = gn1[t] * rsqrtf((float)v + BNEPS);
        sc[t] = s; sh[t] = bn1v[t] - (float)m*s;
        bb[t] = bu_i[t];
    }
    // zero g_sh0 for next step (consumed before barrier B)
    if (blockIdx.x == 0 && t >= 32 && t < 64){
        g_sh0[t-32] = 0.0; g_ssh0[t-32] = 0.0;
    }
    __syncthreads();
    {
        float hn[32];
        #pragma unroll
        for (int kk=0;kk<32;kk++) hn[kk] = fmaf(sc[kk], bufA[t*32+kk], sh[kk]);
        float z[32];
        #pragma unroll
        for (int cc=0;cc<32;cc++) z[cc] = bb[cc];
        const float4* W4 = (const float4*)Wu;
        #pragma unroll
        for (int kk=0;kk<32;kk++){
            float xv = hn[kk];
            #pragma unroll
            for (int j=0;j<8;j++){
                float4 wv = W4[kk*8+j];
                z[4*j+0] = fmaf(xv, wv.x, z[4*j+0]);
                z[4*j+1] = fmaf(xv, wv.y, z[4*j+1]);
                z[4*j+2] = fmaf(xv, wv.z, z[4*j+2]);
                z[4*j+3] = fmaf(xv, wv.w, z[4*j+3]);
            }
        }
        __syncthreads();
        #pragma unroll
        for (int cc=0;cc<32;cc++) bufA[t*32+cc] = tanhf(z[cc]);
    }
    __syncthreads();
    for (int idx=t; idx<1024; idx+=128){
        float4 o4 = ((float4*)bufA)[idx];
        ((float4*)(g_x + (size_t)row0*32))[idx] = o4;
        if (is_last) ((float4*)(out + (size_t)row0*32))[idx] = o4;
    }
}

// ----------------------------------------------------------------------
extern "C" void kernel_launch(void* const* d_in, const int* in_sizes, int n_in,
                              void* d_out, int out_size){
    const float* x    = (const float*)d_in[0];
    const float* Wah  = (const float*)d_in[1];
    const float* bah  = (const float*)d_in[2];
    const float* Wa   = (const float*)d_in[3];
    const float* ba   = (const float*)d_in[4];
    const float* geh  = (const float*)d_in[5];
    const float* beh  = (const float*)d_in[6];
    const float* ge   = (const float*)d_in[7];
    const float* be   = (const float*)d_in[8];
    const float* Wn0  = (const float*)d_in[9];
    const float* bn0  = (const float*)d_in[10];
    const float* Wn   = (const float*)d_in[11];
    const float* bnn  = (const float*)d_in[12];
    const float* gn   = (const float*)d_in[13];
    const float* bnv  = (const float*)d_in[14];
    const float* Wu   = (const float*)d_in[15];
    const float* bu   = (const float*)d_in[16];
    float* out = (float*)d_out;

    cudaFuncSetAttribute(k_edge_main, cudaFuncAttributeMaxDynamicSharedMemorySize, SMEM_MAIN_BYTES);
    cudaFuncSetAttribute(k_nodes, cudaFuncAttributeMaxDynamicSharedMemorySize, SMEM_NODE_BYTES);

    k_pad<<<NT*HH/256, 256>>>(x);

    for (int i=0; i<4; i++){
        k_pre<<<128,256>>>(Wah + i*66*64, bah + i*64);
        k_edge_main<<<dim3(4,64),256,SMEM_MAIN_BYTES>>>(Wah + i*66*64,
                                                        Wa + i*64*32, ba + i*32,
                                                        geh + i*64, beh + i*64, i);
        k_nodes<<<64,128,SMEM_NODE_BYTES>>>(Wn0 + i*64*32, bn0 + i*32,
                                            ge + i*32, be + i*32,
                                            Wn + i*32*32, bnn + i*32,
                                            gn + (i*2+0)*32, bnv + (i*2+0)*32,
                                            Wu + i*32*32, bu + i*32,
                                            gn + (i*2+1)*32, bnv + (i*2+1)*32,
                                            out, (i==3) ? 1 : 0, i);
    }
}